// round 2
// baseline (speedup 1.0000x reference)
#include <cuda_runtime.h>
#include <cstdint>

#define C 64
#define MAXN 50000
#define MAXE 800000

// ---------------- device scratch (static: no allocation allowed) ----------------
__device__ float g_v[MAXN * C];
__device__ float g_Q1[MAXN * C];
__device__ float g_K1[MAXN * C];
__device__ float g_P1[MAXN * C];
__device__ float g_num[MAXN * C];
__device__ float g_den[MAXN * C];
__device__ float g_Mq_t[C * C];   // transposed (att_w1 @ W_dst)
__device__ float g_Mk_t[C * C];   // transposed (att_w1 @ W_src)
__device__ float g_Win_t[C * C];
__device__ float g_Wlin_t[C * C];
__device__ float g_w2a_t[C * C];  // att_w2 transposed: [j][c]
__device__ float g_w2p_t[C * C];  // pos_w2 transposed
__device__ float g_Wout_t[C * C];
__device__ float g_delta0[C];     // pos_mlp(0) constant

// ---------------- K0: weight prep (combined matrices, transposes, delta0) -------
__global__ void prep_kernel(const float* __restrict__ att_w1,
                            const float* __restrict__ W_dst,
                            const float* __restrict__ W_src,
                            const float* __restrict__ W_in,
                            const float* __restrict__ W_lin,
                            const float* __restrict__ att_w2,
                            const float* __restrict__ pos_w2,
                            const float* __restrict__ W_out,
                            const float* __restrict__ pos_b1,
                            const float* __restrict__ pos_b2)
{
    __shared__ float s_a[C * C];
    __shared__ float s_d[C * C];
    __shared__ float s_s[C * C];
    int tid = threadIdx.x;
    for (int t = tid; t < C * C; t += blockDim.x) {
        s_a[t] = att_w1[t];
        s_d[t] = W_dst[t];
        s_s[t] = W_src[t];
    }
    __syncthreads();
    // M_q[t][j] = sum_u att_w1[t][u] * W_dst[u][j]  (store transposed [j][t])
    for (int idx = tid; idx < C * C; idx += blockDim.x) {
        int t = idx >> 6, j = idx & 63;
        float aq = 0.f, ak = 0.f;
        #pragma unroll 8
        for (int u = 0; u < C; u++) {
            float a = s_a[t * C + u];
            aq = fmaf(a, s_d[u * C + j], aq);
            ak = fmaf(a, s_s[u * C + j], ak);
        }
        g_Mq_t[j * C + t] = aq;
        g_Mk_t[j * C + t] = ak;
    }
    // transposed copies of the fixed weights
    for (int idx = tid; idx < C * C; idx += blockDim.x) {
        int cc = idx >> 6, j = idx & 63;
        g_Win_t[j * C + cc]  = W_in[idx];
        g_Wlin_t[j * C + cc] = W_lin[idx];
        g_w2a_t[j * C + cc]  = att_w2[idx];
        g_w2p_t[j * C + cc]  = pos_w2[idx];
        g_Wout_t[j * C + cc] = W_out[idx];
    }
    // delta0 = relu(pos_w2 @ relu(pos_b1) + pos_b2)
    if (tid < C) {
        float acc = pos_b2[tid];
        #pragma unroll 8
        for (int j = 0; j < C; j++)
            acc = fmaf(fmaxf(pos_b1[j], 0.f), pos_w2[tid * C + j], acc);
        g_delta0[tid] = fmaxf(acc, 0.f);
    }
}

// ---------------- K1: per-node projections + self-loop init --------------------
// warp per node; lane owns channels (lane, lane+32); weights in smem [j][c]
__global__ void node_kernel(const float* __restrict__ x,
                            const float* __restrict__ pos,
                            const float* __restrict__ pos_w1,
                            const float* __restrict__ b_in,
                            const float* __restrict__ att_b1,
                            const float* __restrict__ att_b2,
                            int n)
{
    extern __shared__ float sm[];
    float* sWin  = sm;
    float* sWlin = sm + 4096;
    float* sMq   = sm + 8192;
    float* sMk   = sm + 12288;
    float* sW2a  = sm + 16384;
    float* scr   = sm + 20480;  // 4 warps * 64
    for (int t = threadIdx.x; t < 4096; t += blockDim.x) {
        sWin[t]  = g_Win_t[t];
        sWlin[t] = g_Wlin_t[t];
        sMq[t]   = g_Mq_t[t];
        sMk[t]   = g_Mk_t[t];
        sW2a[t]  = g_w2a_t[t];
    }
    __syncthreads();
    int lane = threadIdx.x & 31;
    int w    = threadIdx.x >> 5;
    int c2   = lane + 32;
    float* sc = scr + w * 64;
    int gw = blockIdx.x * 4 + w;
    int nw = gridDim.x * 4;

    float bi0 = b_in[lane],   bi1 = b_in[c2];
    float ba0 = att_b1[lane], ba1 = att_b1[c2];
    float b20 = att_b2[lane], b21 = att_b2[c2];
    float d00 = g_delta0[lane], d01 = g_delta0[c2];
    float pw00 = pos_w1[lane * 3 + 0], pw01 = pos_w1[lane * 3 + 1], pw02 = pos_w1[lane * 3 + 2];
    float pw10 = pos_w1[c2 * 3 + 0],   pw11 = pos_w1[c2 * 3 + 1],   pw12 = pos_w1[c2 * 3 + 2];

    for (int i = gw; i < n; i += nw) {
        size_t o = (size_t)i * C;
        __syncwarp();
        sc[lane] = x[o + lane];
        sc[c2]   = x[o + c2];
        __syncwarp();
        float h0 = bi0, h1 = bi1;
        #pragma unroll
        for (int j = 0; j < C; j++) {
            float xj = sc[j];
            h0 = fmaf(xj, sWin[j * C + lane], h0);
            h1 = fmaf(xj, sWin[j * C + c2],   h1);
        }
        h0 = fmaxf(h0, 0.f); h1 = fmaxf(h1, 0.f);
        __syncwarp();
        sc[lane] = h0; sc[c2] = h1;
        __syncwarp();
        float v0 = 0.f, v1 = 0.f, q0 = 0.f, q1 = 0.f, k0 = 0.f, k1 = 0.f;
        #pragma unroll
        for (int j = 0; j < C; j++) {
            float hj = sc[j];
            v0 = fmaf(hj, sWlin[j * C + lane], v0);
            v1 = fmaf(hj, sWlin[j * C + c2],   v1);
            q0 = fmaf(hj, sMq[j * C + lane],   q0);
            q1 = fmaf(hj, sMq[j * C + c2],     q1);
            k0 = fmaf(hj, sMk[j * C + lane],   k0);
            k1 = fmaf(hj, sMk[j * C + c2],     k1);
        }
        g_v[o + lane]  = v0; g_v[o + c2]  = v1;
        g_Q1[o + lane] = q0; g_Q1[o + c2] = q1;
        g_K1[o + lane] = k0; g_K1[o + c2] = k1;
        float px = pos[(size_t)i * 3 + 0];
        float py = pos[(size_t)i * 3 + 1];
        float pz = pos[(size_t)i * 3 + 2];
        g_P1[o + lane] = px * pw00 + py * pw01 + pz * pw02;
        g_P1[o + c2]   = px * pw10 + py * pw11 + pz * pw12;
        // self-loop attention: relu(att_w2 @ relu(Q1-K1+b1) + b2)
        float a0 = fmaxf(q0 - k0 + ba0, 0.f);
        float a1 = fmaxf(q1 - k1 + ba1, 0.f);
        __syncwarp();
        sc[lane] = a0; sc[c2] = a1;
        __syncwarp();
        float s0 = b20, s1 = b21;
        #pragma unroll
        for (int j = 0; j < C; j++) {
            float aj = sc[j];
            s0 = fmaf(aj, sW2a[j * C + lane], s0);
            s1 = fmaf(aj, sW2a[j * C + c2],   s1);
        }
        float e0 = __expf(fmaxf(s0, 0.f));
        float e1 = __expf(fmaxf(s1, 0.f));
        g_den[o + lane] = e0;             g_den[o + c2] = e1;
        g_num[o + lane] = e0 * (v0 + d00); g_num[o + c2] = e1 * (v1 + d01);
    }
}

// ---------------- K2: edge kernel — gather, 2x (64e x 64c x 64j) GEMM, scatter --
__global__ void __launch_bounds__(256)
edge_kernel(const int* __restrict__ src, const int* __restrict__ dst,
            const float* __restrict__ att_b1, const float* __restrict__ pos_b1,
            const float* __restrict__ att_b2, const float* __restrict__ pos_b2,
            int E)
{
    extern __shared__ float sm[];
    float* w2a  = sm;                    // [j][c] 64x64
    float* w2p  = sm + 4096;
    float* hidA = sm + 8192;             // [e][j] pitch 68
    float* hidP = sm + 8192 + 64 * 68;
    __shared__ int se[64], de[64];

    for (int t = threadIdx.x; t < 4096; t += 256) {
        w2a[t] = g_w2a_t[t];
        w2p[t] = g_w2p_t[t];
    }
    __syncthreads();

    int tid = threadIdx.x;
    int ntiles = (E + 63) >> 6;
    for (int tile = blockIdx.x; tile < ntiles; tile += gridDim.x) {
        int base = tile << 6;
        if (tid < 64) {
            int e = base + tid;
            if (e < E) { se[tid] = src[e]; de[tid] = dst[e]; }
            else       { se[tid] = 0;      de[tid] = -1;     }
        }
        __syncthreads();
        // ---- gather + first-layer-residual -> hidden activations ----
        {
            int e  = tid >> 2;
            int j0 = (tid & 3) << 4;
            int d  = de[e];
            int dc = d < 0 ? 0 : d;
            int s  = se[e];
            const float* Qr = g_Q1 + (size_t)dc * C;
            const float* Kr = g_K1 + (size_t)s  * C;
            const float* Pd = g_P1 + (size_t)dc * C;
            const float* Ps = g_P1 + (size_t)s  * C;
            #pragma unroll
            for (int gq = 0; gq < 4; gq++) {
                int j = j0 + gq * 4;
                float4 qv = *(const float4*)(Qr + j);
                float4 kv = *(const float4*)(Kr + j);
                float4 ba = *(const float4*)(att_b1 + j);
                float4 r;
                r.x = fmaxf(qv.x - kv.x + ba.x, 0.f);
                r.y = fmaxf(qv.y - kv.y + ba.y, 0.f);
                r.z = fmaxf(qv.z - kv.z + ba.z, 0.f);
                r.w = fmaxf(qv.w - kv.w + ba.w, 0.f);
                *(float4*)(hidA + e * 68 + j) = r;
                float4 pd = *(const float4*)(Pd + j);
                float4 ps = *(const float4*)(Ps + j);
                float4 bp = *(const float4*)(pos_b1 + j);
                r.x = fmaxf(pd.x - ps.x + bp.x, 0.f);
                r.y = fmaxf(pd.y - ps.y + bp.y, 0.f);
                r.z = fmaxf(pd.z - ps.z + bp.z, 0.f);
                r.w = fmaxf(pd.w - ps.w + bp.w, 0.f);
                *(float4*)(hidP + e * 68 + j) = r;
            }
        }
        __syncthreads();
        // ---- two 64x64x64 GEMMs, 4x4 register tiles, then exp + atomics ----
        {
            int ct = tid & 15, eg = tid >> 4;
            int c0 = ct << 2,  e0 = eg << 2;
            float4 accA[4], accP[4];
            float4 bA = *(const float4*)(att_b2 + c0);
            float4 bP = *(const float4*)(pos_b2 + c0);
            #pragma unroll
            for (int k = 0; k < 4; k++) { accA[k] = bA; accP[k] = bP; }
            #pragma unroll 4
            for (int j4 = 0; j4 < C; j4 += 4) {
                float4 ha[4], hp[4];
                #pragma unroll
                for (int k = 0; k < 4; k++) {
                    ha[k] = *(const float4*)(hidA + (e0 + k) * 68 + j4);
                    hp[k] = *(const float4*)(hidP + (e0 + k) * 68 + j4);
                }
                #pragma unroll
                for (int jj = 0; jj < 4; jj++) {
                    float4 wa = *(const float4*)(w2a + (j4 + jj) * C + c0);
                    float4 wp = *(const float4*)(w2p + (j4 + jj) * C + c0);
                    #pragma unroll
                    for (int k = 0; k < 4; k++) {
                        float hv = ((const float*)&ha[k])[jj];
                        accA[k].x = fmaf(hv, wa.x, accA[k].x);
                        accA[k].y = fmaf(hv, wa.y, accA[k].y);
                        accA[k].z = fmaf(hv, wa.z, accA[k].z);
                        accA[k].w = fmaf(hv, wa.w, accA[k].w);
                        float pv = ((const float*)&hp[k])[jj];
                        accP[k].x = fmaf(pv, wp.x, accP[k].x);
                        accP[k].y = fmaf(pv, wp.y, accP[k].y);
                        accP[k].z = fmaf(pv, wp.z, accP[k].z);
                        accP[k].w = fmaf(pv, wp.w, accP[k].w);
                    }
                }
            }
            #pragma unroll
            for (int k = 0; k < 4; k++) {
                int e = e0 + k;
                int d = de[e];
                if (d >= 0) {
                    int s = se[e];
                    float4 vv = *(const float4*)(g_v + (size_t)s * C + c0);
                    float* nr = g_num + (size_t)d * C + c0;
                    float* dr = g_den + (size_t)d * C + c0;
                    float ex0 = __expf(fmaxf(accA[k].x, 0.f));
                    float ex1 = __expf(fmaxf(accA[k].y, 0.f));
                    float ex2 = __expf(fmaxf(accA[k].z, 0.f));
                    float ex3 = __expf(fmaxf(accA[k].w, 0.f));
                    atomicAdd(nr + 0, ex0 * (vv.x + fmaxf(accP[k].x, 0.f)));
                    atomicAdd(nr + 1, ex1 * (vv.y + fmaxf(accP[k].y, 0.f)));
                    atomicAdd(nr + 2, ex2 * (vv.z + fmaxf(accP[k].z, 0.f)));
                    atomicAdd(nr + 3, ex3 * (vv.w + fmaxf(accP[k].w, 0.f)));
                    atomicAdd(dr + 0, ex0);
                    atomicAdd(dr + 1, ex1);
                    atomicAdd(dr + 2, ex2);
                    atomicAdd(dr + 3, ex3);
                }
            }
        }
        __syncthreads();
    }
}

// ---------------- K3: normalize + output projection + relu ---------------------
__global__ void out_kernel(const float* __restrict__ b_out, float* __restrict__ out, int n)
{
    __shared__ float sW[4096];
    __shared__ float scr[4][64];
    for (int t = threadIdx.x; t < 4096; t += blockDim.x) sW[t] = g_Wout_t[t];
    __syncthreads();
    int lane = threadIdx.x & 31, w = threadIdx.x >> 5;
    int c2 = lane + 32;
    float bo0 = b_out[lane], bo1 = b_out[c2];
    int gw = blockIdx.x * 4 + w, nw = gridDim.x * 4;
    float* sc = scr[w];
    for (int i = gw; i < n; i += nw) {
        size_t o = (size_t)i * C;
        __syncwarp();
        sc[lane] = g_num[o + lane] / (g_den[o + lane] + 1e-16f);
        sc[c2]   = g_num[o + c2]   / (g_den[o + c2]   + 1e-16f);
        __syncwarp();
        float s0 = bo0, s1 = bo1;
        #pragma unroll
        for (int j = 0; j < C; j++) {
            float rj = sc[j];
            s0 = fmaf(rj, sW[j * C + lane], s0);
            s1 = fmaf(rj, sW[j * C + c2],   s1);
        }
        out[o + lane] = fmaxf(s0, 0.f);
        out[o + c2]   = fmaxf(s1, 0.f);
    }
}

// ---------------- launch --------------------------------------------------------
extern "C" void kernel_launch(void* const* d_in, const int* in_sizes, int n_in,
                              void* d_out, int out_size)
{
    const float* x      = (const float*)d_in[0];
    const float* pos    = (const float*)d_in[1];
    const int*   ei     = (const int*)  d_in[2];
    const float* W_in   = (const float*)d_in[3];
    const float* b_in   = (const float*)d_in[4];
    const float* W_out  = (const float*)d_in[5];
    const float* b_out  = (const float*)d_in[6];
    const float* W_lin  = (const float*)d_in[7];
    const float* W_src  = (const float*)d_in[8];
    const float* W_dst  = (const float*)d_in[9];
    const float* pos_w1 = (const float*)d_in[10];
    const float* pos_b1 = (const float*)d_in[11];
    const float* pos_w2 = (const float*)d_in[12];
    const float* pos_b2 = (const float*)d_in[13];
    const float* att_w1 = (const float*)d_in[14];
    const float* att_b1 = (const float*)d_in[15];
    const float* att_w2 = (const float*)d_in[16];
    const float* att_b2 = (const float*)d_in[17];

    int n = in_sizes[0] / C;
    int E = in_sizes[2] / 2;
    const int* srcArr = ei;
    const int* dstArr = ei + E;

    static int configured = 0;
    // idempotent; safe to call every launch (not a stream op)
    size_t smemNode = (size_t)(5 * 4096 + 4 * 64) * sizeof(float);           // 82944
    size_t smemEdge = (size_t)(2 * 4096 + 2 * 64 * 68) * sizeof(float);      // 67584
    cudaFuncSetAttribute(node_kernel, cudaFuncAttributeMaxDynamicSharedMemorySize, (int)smemNode);
    cudaFuncSetAttribute(edge_kernel, cudaFuncAttributeMaxDynamicSharedMemorySize, (int)smemEdge);
    (void)configured;

    prep_kernel<<<1, 256>>>(att_w1, W_dst, W_src, W_in, W_lin, att_w2, pos_w2, W_out,
                            pos_b1, pos_b2);
    node_kernel<<<1024, 128, smemNode>>>(x, pos, pos_w1, b_in, att_b1, att_b2, n);
    edge_kernel<<<888, 256, smemEdge>>>(srcArr, dstArr, att_b1, pos_b1, att_b2, pos_b2, E);
    out_kernel<<<1024, 128>>>(b_out, (float*)d_out, n);
}

// round 3
// speedup vs baseline: 1.3977x; 1.3977x over previous
#include <cuda_runtime.h>
#include <cstdint>

#define C 64
#define MAXN 50000
#define MAXE 800000

// ---------------- device scratch (static: no allocation allowed) ----------------
__device__ float g_v[MAXN * C];
__device__ float g_Q1[MAXN * C];
__device__ float g_K1[MAXN * C];
__device__ float g_P1[MAXN * C];
__device__ float g_num[MAXN * C];
__device__ float g_den[MAXN * C];
__device__ float g_Mq_t[C * C];   // transposed (att_w1 @ W_dst)
__device__ float g_Mk_t[C * C];   // transposed (att_w1 @ W_src)
__device__ float g_Win_t[C * C];
__device__ float g_Wlin_t[C * C];
__device__ float g_w2a_t[C * C];  // att_w2 transposed: [j][c]  (j = hidden = K, c = out = N)
__device__ float g_w2p_t[C * C];  // pos_w2 transposed
__device__ float g_Wout_t[C * C];
__device__ float g_delta0[C];     // pos_mlp(0) constant

// ---------------- K0: weight prep (combined matrices, transposes, delta0) -------
__global__ void prep_kernel(const float* __restrict__ att_w1,
                            const float* __restrict__ W_dst,
                            const float* __restrict__ W_src,
                            const float* __restrict__ W_in,
                            const float* __restrict__ W_lin,
                            const float* __restrict__ att_w2,
                            const float* __restrict__ pos_w2,
                            const float* __restrict__ W_out,
                            const float* __restrict__ pos_b1,
                            const float* __restrict__ pos_b2)
{
    __shared__ float s_a[C * C];
    __shared__ float s_d[C * C];
    __shared__ float s_s[C * C];
    int tid = threadIdx.x;
    for (int t = tid; t < C * C; t += blockDim.x) {
        s_a[t] = att_w1[t];
        s_d[t] = W_dst[t];
        s_s[t] = W_src[t];
    }
    __syncthreads();
    for (int idx = tid; idx < C * C; idx += blockDim.x) {
        int t = idx >> 6, j = idx & 63;
        float aq = 0.f, ak = 0.f;
        #pragma unroll 8
        for (int u = 0; u < C; u++) {
            float a = s_a[t * C + u];
            aq = fmaf(a, s_d[u * C + j], aq);
            ak = fmaf(a, s_s[u * C + j], ak);
        }
        g_Mq_t[j * C + t] = aq;
        g_Mk_t[j * C + t] = ak;
    }
    for (int idx = tid; idx < C * C; idx += blockDim.x) {
        int cc = idx >> 6, j = idx & 63;
        g_Win_t[j * C + cc]  = W_in[idx];
        g_Wlin_t[j * C + cc] = W_lin[idx];
        g_w2a_t[j * C + cc]  = att_w2[idx];
        g_w2p_t[j * C + cc]  = pos_w2[idx];
        g_Wout_t[j * C + cc] = W_out[idx];
    }
    if (tid < C) {
        float acc = pos_b2[tid];
        #pragma unroll 8
        for (int j = 0; j < C; j++)
            acc = fmaf(fmaxf(pos_b1[j], 0.f), pos_w2[tid * C + j], acc);
        g_delta0[tid] = fmaxf(acc, 0.f);
    }
}

// ---------------- K1: per-node projections + self-loop init --------------------
__global__ void node_kernel(const float* __restrict__ x,
                            const float* __restrict__ pos,
                            const float* __restrict__ pos_w1,
                            const float* __restrict__ b_in,
                            const float* __restrict__ att_b1,
                            const float* __restrict__ att_b2,
                            int n)
{
    extern __shared__ float sm[];
    float* sWin  = sm;
    float* sWlin = sm + 4096;
    float* sMq   = sm + 8192;
    float* sMk   = sm + 12288;
    float* sW2a  = sm + 16384;
    float* scr   = sm + 20480;
    for (int t = threadIdx.x; t < 4096; t += blockDim.x) {
        sWin[t]  = g_Win_t[t];
        sWlin[t] = g_Wlin_t[t];
        sMq[t]   = g_Mq_t[t];
        sMk[t]   = g_Mk_t[t];
        sW2a[t]  = g_w2a_t[t];
    }
    __syncthreads();
    int lane = threadIdx.x & 31;
    int w    = threadIdx.x >> 5;
    int c2   = lane + 32;
    float* sc = scr + w * 64;
    int gw = blockIdx.x * 4 + w;
    int nw = gridDim.x * 4;

    float bi0 = b_in[lane],   bi1 = b_in[c2];
    float ba0 = att_b1[lane], ba1 = att_b1[c2];
    float b20 = att_b2[lane], b21 = att_b2[c2];
    float d00 = g_delta0[lane], d01 = g_delta0[c2];
    float pw00 = pos_w1[lane * 3 + 0], pw01 = pos_w1[lane * 3 + 1], pw02 = pos_w1[lane * 3 + 2];
    float pw10 = pos_w1[c2 * 3 + 0],   pw11 = pos_w1[c2 * 3 + 1],   pw12 = pos_w1[c2 * 3 + 2];

    for (int i = gw; i < n; i += nw) {
        size_t o = (size_t)i * C;
        __syncwarp();
        sc[lane] = x[o + lane];
        sc[c2]   = x[o + c2];
        __syncwarp();
        float h0 = bi0, h1 = bi1;
        #pragma unroll
        for (int j = 0; j < C; j++) {
            float xj = sc[j];
            h0 = fmaf(xj, sWin[j * C + lane], h0);
            h1 = fmaf(xj, sWin[j * C + c2],   h1);
        }
        h0 = fmaxf(h0, 0.f); h1 = fmaxf(h1, 0.f);
        __syncwarp();
        sc[lane] = h0; sc[c2] = h1;
        __syncwarp();
        float v0 = 0.f, v1 = 0.f, q0 = 0.f, q1 = 0.f, k0 = 0.f, k1 = 0.f;
        #pragma unroll
        for (int j = 0; j < C; j++) {
            float hj = sc[j];
            v0 = fmaf(hj, sWlin[j * C + lane], v0);
            v1 = fmaf(hj, sWlin[j * C + c2],   v1);
            q0 = fmaf(hj, sMq[j * C + lane],   q0);
            q1 = fmaf(hj, sMq[j * C + c2],     q1);
            k0 = fmaf(hj, sMk[j * C + lane],   k0);
            k1 = fmaf(hj, sMk[j * C + c2],     k1);
        }
        g_v[o + lane]  = v0; g_v[o + c2]  = v1;
        g_Q1[o + lane] = q0; g_Q1[o + c2] = q1;
        g_K1[o + lane] = k0; g_K1[o + c2] = k1;
        float px = pos[(size_t)i * 3 + 0];
        float py = pos[(size_t)i * 3 + 1];
        float pz = pos[(size_t)i * 3 + 2];
        g_P1[o + lane] = px * pw00 + py * pw01 + pz * pw02;
        g_P1[o + c2]   = px * pw10 + py * pw11 + pz * pw12;
        float a0 = fmaxf(q0 - k0 + ba0, 0.f);
        float a1 = fmaxf(q1 - k1 + ba1, 0.f);
        __syncwarp();
        sc[lane] = a0; sc[c2] = a1;
        __syncwarp();
        float s0 = b20, s1 = b21;
        #pragma unroll
        for (int j = 0; j < C; j++) {
            float aj = sc[j];
            s0 = fmaf(aj, sW2a[j * C + lane], s0);
            s1 = fmaf(aj, sW2a[j * C + c2],   s1);
        }
        float e0 = __expf(fmaxf(s0, 0.f));
        float e1 = __expf(fmaxf(s1, 0.f));
        g_den[o + lane] = e0;             g_den[o + c2] = e1;
        g_num[o + lane] = e0 * (v0 + d00); g_num[o + c2] = e1 * (v1 + d01);
    }
}

// ---------------- K2: edge kernel — gather, 2x tf32 tensor-core GEMM, scatter ---
#define MMA_TF32(d, a, b0, b1)                                               \
    asm volatile("mma.sync.aligned.m16n8k8.row.col.f32.tf32.tf32.f32 "       \
                 "{%0,%1,%2,%3}, {%4,%5,%6,%7}, {%8,%9}, {%0,%1,%2,%3};"     \
                 : "+f"(d[0]), "+f"(d[1]), "+f"(d[2]), "+f"(d[3])            \
                 : "r"(a[0]), "r"(a[1]), "r"(a[2]), "r"(a[3]),               \
                   "r"(b0), "r"(b1))

__device__ __forceinline__ unsigned f2tf32(float f) {
    unsigned r;
    asm("cvt.rna.tf32.f32 %0, %1;" : "=r"(r) : "f"(f));
    return r;
}

__global__ void __launch_bounds__(256, 2)
edge_kernel(const int* __restrict__ src, const int* __restrict__ dst,
            const float* __restrict__ att_b1, const float* __restrict__ pos_b1,
            const float* __restrict__ att_b2, const float* __restrict__ pos_b2,
            int E)
{
    __shared__ float hidA[64 * 68];   // also reused as exp(alpha) buffer
    __shared__ float hidP[64 * 68];   // also reused as delta buffer
    __shared__ int se[64], de[64];

    int tid  = threadIdx.x;
    int lane = tid & 31;
    int wid  = tid >> 5;
    bool isA = (wid < 4);
    int sub  = wid & 3;
    int n0b  = (sub & 1) * 32;            // 32-col half handled by this warp
    int mp   = sub >> 1;
    int r0   = mp * 16;                    // two 16-row stripes
    int r1   = (mp + 2) * 16;

    const float* w2 = isA ? g_w2a_t : g_w2p_t;
    const float* b2 = isA ? att_b2 : pos_b2;
    float* hid = isA ? hidA : hidP;

    // --- preload B fragments (weights, tf32) into registers; reused every tile ---
    unsigned bB[8][4][2];
    #pragma unroll
    for (int kt = 0; kt < 8; kt++) {
        #pragma unroll
        for (int nt = 0; nt < 4; nt++) {
            int k0 = kt * 8, n0 = n0b + nt * 8;
            bB[kt][nt][0] = f2tf32(w2[(k0 + (lane & 3)) * 64 + n0 + (lane >> 2)]);
            bB[kt][nt][1] = f2tf32(w2[(k0 + (lane & 3) + 4) * 64 + n0 + (lane >> 2)]);
        }
    }
    float bias0[4], bias1[4];
    #pragma unroll
    for (int nt = 0; nt < 4; nt++) {
        int col = n0b + nt * 8 + 2 * (lane & 3);
        bias0[nt] = b2[col];
        bias1[nt] = b2[col + 1];
    }

    int ntiles = (E + 63) >> 6;
    for (int tile = blockIdx.x; tile < ntiles; tile += gridDim.x) {
        int base = tile << 6;
        if (tid < 64) {
            int e = base + tid;
            if (e < E) { se[tid] = src[e]; de[tid] = dst[e]; }
            else       { se[tid] = 0;      de[tid] = -1;     }
        }
        __syncthreads();

        // ---- gather + first-layer residual -> tf32 hidden activations ----
        {
            int e  = tid >> 2;
            int j0 = (tid & 3) << 4;
            int d  = de[e];
            int dc = d < 0 ? 0 : d;
            int s  = se[e];
            const float* Qr = g_Q1 + (size_t)dc * C;
            const float* Kr = g_K1 + (size_t)s  * C;
            const float* Pd = g_P1 + (size_t)dc * C;
            const float* Ps = g_P1 + (size_t)s  * C;
            #pragma unroll
            for (int gq = 0; gq < 4; gq++) {
                int j = j0 + gq * 4;
                float4 qv = *(const float4*)(Qr + j);
                float4 kv = *(const float4*)(Kr + j);
                float4 ba = *(const float4*)(att_b1 + j);
                float4 r;
                r.x = __uint_as_float(f2tf32(fmaxf(qv.x - kv.x + ba.x, 0.f)));
                r.y = __uint_as_float(f2tf32(fmaxf(qv.y - kv.y + ba.y, 0.f)));
                r.z = __uint_as_float(f2tf32(fmaxf(qv.z - kv.z + ba.z, 0.f)));
                r.w = __uint_as_float(f2tf32(fmaxf(qv.w - kv.w + ba.w, 0.f)));
                *(float4*)(hidA + e * 68 + j) = r;
                float4 pd = *(const float4*)(Pd + j);
                float4 ps = *(const float4*)(Ps + j);
                float4 bp = *(const float4*)(pos_b1 + j);
                r.x = __uint_as_float(f2tf32(fmaxf(pd.x - ps.x + bp.x, 0.f)));
                r.y = __uint_as_float(f2tf32(fmaxf(pd.y - ps.y + bp.y, 0.f)));
                r.z = __uint_as_float(f2tf32(fmaxf(pd.z - ps.z + bp.z, 0.f)));
                r.w = __uint_as_float(f2tf32(fmaxf(pd.w - ps.w + bp.w, 0.f)));
                *(float4*)(hidP + e * 68 + j) = r;
            }
        }
        __syncthreads();

        // ---- tensor-core GEMM: D[64e x 64c] = hid[64e x 64j] @ W2t[64j x 64c] ----
        float acc[2][4][4];
        #pragma unroll
        for (int s2 = 0; s2 < 2; s2++)
            #pragma unroll
            for (int nt = 0; nt < 4; nt++) {
                acc[s2][nt][0] = bias0[nt];
                acc[s2][nt][1] = bias1[nt];
                acc[s2][nt][2] = bias0[nt];
                acc[s2][nt][3] = bias1[nt];
            }
        int rA = lane >> 2;
        #pragma unroll
        for (int kt = 0; kt < 8; kt++) {
            int cA = kt * 8 + (lane & 3);
            unsigned a[2][4];
            a[0][0] = __float_as_uint(hid[(r0 + rA) * 68 + cA]);
            a[0][1] = __float_as_uint(hid[(r0 + 8 + rA) * 68 + cA]);
            a[0][2] = __float_as_uint(hid[(r0 + rA) * 68 + cA + 4]);
            a[0][3] = __float_as_uint(hid[(r0 + 8 + rA) * 68 + cA + 4]);
            a[1][0] = __float_as_uint(hid[(r1 + rA) * 68 + cA]);
            a[1][1] = __float_as_uint(hid[(r1 + 8 + rA) * 68 + cA]);
            a[1][2] = __float_as_uint(hid[(r1 + rA) * 68 + cA + 4]);
            a[1][3] = __float_as_uint(hid[(r1 + 8 + rA) * 68 + cA + 4]);
            #pragma unroll
            for (int s2 = 0; s2 < 2; s2++)
                #pragma unroll
                for (int nt = 0; nt < 4; nt++)
                    MMA_TF32(acc[s2][nt], a[s2], bB[kt][nt][0], bB[kt][nt][1]);
        }
        __syncthreads();

        // ---- transform + write back to smem (reuse hid buffers) ----
        {
            int cb = 2 * (lane & 3);
            #pragma unroll
            for (int s2 = 0; s2 < 2; s2++) {
                int rb = (s2 ? r1 : r0) + rA;
                #pragma unroll
                for (int nt = 0; nt < 4; nt++) {
                    int col = n0b + nt * 8 + cb;
                    float v0, v1, v2, v3;
                    if (isA) {
                        v0 = __expf(fmaxf(acc[s2][nt][0], 0.f));
                        v1 = __expf(fmaxf(acc[s2][nt][1], 0.f));
                        v2 = __expf(fmaxf(acc[s2][nt][2], 0.f));
                        v3 = __expf(fmaxf(acc[s2][nt][3], 0.f));
                    } else {
                        v0 = fmaxf(acc[s2][nt][0], 0.f);
                        v1 = fmaxf(acc[s2][nt][1], 0.f);
                        v2 = fmaxf(acc[s2][nt][2], 0.f);
                        v3 = fmaxf(acc[s2][nt][3], 0.f);
                    }
                    hid[rb * 68 + col]       = v0;
                    hid[rb * 68 + col + 1]   = v1;
                    hid[(rb + 8) * 68 + col]     = v2;
                    hid[(rb + 8) * 68 + col + 1] = v3;
                }
            }
        }
        __syncthreads();

        // ---- scatter: num += exp*(v+delta), den += exp   (vector red) ----
        {
            int e0 = (tid >> 4) << 2;
            int c0 = (tid & 15) << 2;
            #pragma unroll
            for (int k = 0; k < 4; k++) {
                int e = e0 + k;
                int d = de[e];
                if (d >= 0) {
                    int s = se[e];
                    float4 ex = *(const float4*)(hidA + e * 68 + c0);
                    float4 dl = *(const float4*)(hidP + e * 68 + c0);
                    float4 vv = *(const float4*)(g_v + (size_t)s * C + c0);
                    float n0_ = ex.x * (vv.x + dl.x);
                    float n1_ = ex.y * (vv.y + dl.y);
                    float n2_ = ex.z * (vv.z + dl.z);
                    float n3_ = ex.w * (vv.w + dl.w);
                    float* nr = g_num + (size_t)d * C + c0;
                    float* dr = g_den + (size_t)d * C + c0;
                    asm volatile("red.global.add.v4.f32 [%0], {%1,%2,%3,%4};"
                                 :: "l"(nr), "f"(n0_), "f"(n1_), "f"(n2_), "f"(n3_)
                                 : "memory");
                    asm volatile("red.global.add.v4.f32 [%0], {%1,%2,%3,%4};"
                                 :: "l"(dr), "f"(ex.x), "f"(ex.y), "f"(ex.z), "f"(ex.w)
                                 : "memory");
                }
            }
        }
        __syncthreads();
    }
}

// ---------------- K3: normalize + output projection + relu ---------------------
__global__ void out_kernel(const float* __restrict__ b_out, float* __restrict__ out, int n)
{
    __shared__ float sW[4096];
    __shared__ float scr[4][64];
    for (int t = threadIdx.x; t < 4096; t += blockDim.x) sW[t] = g_Wout_t[t];
    __syncthreads();
    int lane = threadIdx.x & 31, w = threadIdx.x >> 5;
    int c2 = lane + 32;
    float bo0 = b_out[lane], bo1 = b_out[c2];
    int gw = blockIdx.x * 4 + w, nw = gridDim.x * 4;
    float* sc = scr[w];
    for (int i = gw; i < n; i += nw) {
        size_t o = (size_t)i * C;
        __syncwarp();
        sc[lane] = g_num[o + lane] / (g_den[o + lane] + 1e-16f);
        sc[c2]   = g_num[o + c2]   / (g_den[o + c2]   + 1e-16f);
        __syncwarp();
        float s0 = bo0, s1 = bo1;
        #pragma unroll
        for (int j = 0; j < C; j++) {
            float rj = sc[j];
            s0 = fmaf(rj, sW[j * C + lane], s0);
            s1 = fmaf(rj, sW[j * C + c2],   s1);
        }
        out[o + lane] = fmaxf(s0, 0.f);
        out[o + c2]   = fmaxf(s1, 0.f);
    }
}

// ---------------- launch --------------------------------------------------------
extern "C" void kernel_launch(void* const* d_in, const int* in_sizes, int n_in,
                              void* d_out, int out_size)
{
    const float* x      = (const float*)d_in[0];
    const float* pos    = (const float*)d_in[1];
    const int*   ei     = (const int*)  d_in[2];
    const float* W_in   = (const float*)d_in[3];
    const float* b_in   = (const float*)d_in[4];
    const float* W_out  = (const float*)d_in[5];
    const float* b_out  = (const float*)d_in[6];
    const float* W_lin  = (const float*)d_in[7];
    const float* W_src  = (const float*)d_in[8];
    const float* W_dst  = (const float*)d_in[9];
    const float* pos_w1 = (const float*)d_in[10];
    const float* pos_b1 = (const float*)d_in[11];
    const float* pos_w2 = (const float*)d_in[12];
    const float* pos_b2 = (const float*)d_in[13];
    const float* att_w1 = (const float*)d_in[14];
    const float* att_b1 = (const float*)d_in[15];
    const float* att_w2 = (const float*)d_in[16];
    const float* att_b2 = (const float*)d_in[17];

    int n = in_sizes[0] / C;
    int E = in_sizes[2] / 2;
    const int* srcArr = ei;
    const int* dstArr = ei + E;

    size_t smemNode = (size_t)(5 * 4096 + 4 * 64) * sizeof(float);
    cudaFuncSetAttribute(node_kernel, cudaFuncAttributeMaxDynamicSharedMemorySize, (int)smemNode);

    prep_kernel<<<1, 256>>>(att_w1, W_dst, W_src, W_in, W_lin, att_w2, pos_w2, W_out,
                            pos_b1, pos_b2);
    node_kernel<<<1024, 128, smemNode>>>(x, pos, pos_w1, b_in, att_b1, att_b2, n);
    edge_kernel<<<592, 256>>>(srcArr, dstArr, att_b1, pos_b1, att_b2, pos_b2, E);
    out_kernel<<<1024, 128>>>(b_out, (float*)d_out, n);
}

// round 4
// speedup vs baseline: 1.8273x; 1.3074x over previous
#include <cuda_runtime.h>
#include <cstdint>

#define C 64
#define MAXN 50000
#define MAXE 800000

// ---------------- device scratch (static: no allocation allowed) ----------------
__device__ float g_v[MAXN * C];
__device__ float g_Q1[MAXN * C];
__device__ float g_K1[MAXN * C];
__device__ float g_P1[MAXN * C];
__device__ float g_num[MAXN * C];
__device__ float g_den[MAXN * C];
__device__ float g_Mq_t[C * C];
__device__ float g_Mk_t[C * C];
__device__ float g_Win_t[C * C];
__device__ float g_Wlin_t[C * C];
__device__ float g_w2a_t[C * C];
__device__ float g_w2p_t[C * C];
__device__ float g_Wout_t[C * C];
__device__ float g_delta0[C];
// fragment-ordered tf32 weights: [(kt*8+nt)*32+lane] -> float2 (k, k+4)
__device__ float g_fWin[4096];
__device__ float g_fWlin[4096];
__device__ float g_fMq[4096];
__device__ float g_fMk[4096];
__device__ float g_fW2a[4096];
__device__ float g_fWout[4096];

__device__ __forceinline__ unsigned f2tf32(float f) {
    unsigned r;
    asm("cvt.rna.tf32.f32 %0, %1;" : "=r"(r) : "f"(f));
    return r;
}

#define MMA_TF32(d, a, b0, b1)                                               \
    asm volatile("mma.sync.aligned.m16n8k8.row.col.f32.tf32.tf32.f32 "       \
                 "{%0,%1,%2,%3}, {%4,%5,%6,%7}, {%8,%9}, {%0,%1,%2,%3};"     \
                 : "+f"(d[0]), "+f"(d[1]), "+f"(d[2]), "+f"(d[3])            \
                 : "r"(a[0]), "r"(a[1]), "r"(a[2]), "r"(a[3]),               \
                   "r"(b0), "r"(b1))

// ---------------- K0: weight prep ------------------------------------------------
__global__ void prep_kernel(const float* __restrict__ att_w1,
                            const float* __restrict__ W_dst,
                            const float* __restrict__ W_src,
                            const float* __restrict__ W_in,
                            const float* __restrict__ W_lin,
                            const float* __restrict__ att_w2,
                            const float* __restrict__ pos_w2,
                            const float* __restrict__ W_out,
                            const float* __restrict__ pos_b1,
                            const float* __restrict__ pos_b2)
{
    __shared__ float s_a[C * C];
    __shared__ float s_d[C * C];
    __shared__ float s_s[C * C];
    int tid = threadIdx.x;
    for (int t = tid; t < C * C; t += blockDim.x) {
        s_a[t] = att_w1[t];
        s_d[t] = W_dst[t];
        s_s[t] = W_src[t];
    }
    __syncthreads();
    for (int idx = tid; idx < C * C; idx += blockDim.x) {
        int t = idx >> 6, j = idx & 63;
        float aq = 0.f, ak = 0.f;
        #pragma unroll 8
        for (int u = 0; u < C; u++) {
            float a = s_a[t * C + u];
            aq = fmaf(a, s_d[u * C + j], aq);
            ak = fmaf(a, s_s[u * C + j], ak);
        }
        g_Mq_t[j * C + t] = aq;
        g_Mk_t[j * C + t] = ak;
    }
    for (int idx = tid; idx < C * C; idx += blockDim.x) {
        int cc = idx >> 6, j = idx & 63;
        g_Win_t[j * C + cc]  = W_in[idx];
        g_Wlin_t[j * C + cc] = W_lin[idx];
        g_w2a_t[j * C + cc]  = att_w2[idx];
        g_w2p_t[j * C + cc]  = pos_w2[idx];
        g_Wout_t[j * C + cc] = W_out[idx];
    }
    if (tid < C) {
        float acc = pos_b2[tid];
        #pragma unroll 8
        for (int j = 0; j < C; j++)
            acc = fmaf(fmaxf(pos_b1[j], 0.f), pos_w2[tid * C + j], acc);
        g_delta0[tid] = fmaxf(acc, 0.f);
    }
    __syncthreads();   // g_*_t visible to whole block
    // build fragment-ordered tf32 copies
    for (int t = tid; t < 2048; t += blockDim.x) {
        int kt   = t >> 8;
        int nt   = (t >> 5) & 7;
        int lane = t & 31;
        int kr = kt * 8 + (lane & 3);
        int nc = nt * 8 + (lane >> 2);
        int lo = kr * 64 + nc, hi = (kr + 4) * 64 + nc;
        ((float2*)g_fWin)[t]  = make_float2(__uint_as_float(f2tf32(g_Win_t[lo])),
                                            __uint_as_float(f2tf32(g_Win_t[hi])));
        ((float2*)g_fWlin)[t] = make_float2(__uint_as_float(f2tf32(g_Wlin_t[lo])),
                                            __uint_as_float(f2tf32(g_Wlin_t[hi])));
        ((float2*)g_fMq)[t]   = make_float2(__uint_as_float(f2tf32(g_Mq_t[lo])),
                                            __uint_as_float(f2tf32(g_Mq_t[hi])));
        ((float2*)g_fMk)[t]   = make_float2(__uint_as_float(f2tf32(g_Mk_t[lo])),
                                            __uint_as_float(f2tf32(g_Mk_t[hi])));
        ((float2*)g_fW2a)[t]  = make_float2(__uint_as_float(f2tf32(g_w2a_t[lo])),
                                            __uint_as_float(f2tf32(g_w2a_t[hi])));
        ((float2*)g_fWout)[t] = make_float2(__uint_as_float(f2tf32(g_Wout_t[lo])),
                                            __uint_as_float(f2tf32(g_Wout_t[hi])));
    }
}

// ---------------- K1: node kernel — 5 fused tf32 GEMMs over 64-node tiles -------
__global__ void __launch_bounds__(256)
node_kernel(const float* __restrict__ x,
            const float* __restrict__ pos,
            const float* __restrict__ pos_w1,
            const float* __restrict__ b_in,
            const float* __restrict__ att_b1,
            const float* __restrict__ att_b2,
            int n)
{
    extern __shared__ float sm[];
    float* xs = sm;            // 64x68 tf32 x; reused for 'a' later
    float* hs = sm + 4352;     // 64x68 tf32 h
    float* vs = sm + 8704;     // 64x68 fp32 v
    int tid  = threadIdx.x;
    int lane = tid & 31;
    int wid  = tid >> 5;
    int base = blockIdx.x * 64;

    // load x tile -> tf32 smem
    for (int t = tid; t < 1024; t += 256) {
        int row = t >> 4;
        int col = (t & 15) * 4;
        int node = base + row;
        float4 v4 = make_float4(0.f, 0.f, 0.f, 0.f);
        if (node < n) v4 = *(const float4*)(x + (size_t)node * C + col);
        float4 r;
        r.x = __uint_as_float(f2tf32(v4.x));
        r.y = __uint_as_float(f2tf32(v4.y));
        r.z = __uint_as_float(f2tf32(v4.z));
        r.w = __uint_as_float(f2tf32(v4.w));
        *(float4*)(xs + row * 68 + col) = r;
    }
    // P1 = pos @ pos_w1^T  (independent)
    {
        int row = tid >> 2;
        int node = base + row;
        if (node < n) {
            float px = pos[(size_t)node * 3 + 0];
            float py = pos[(size_t)node * 3 + 1];
            float pz = pos[(size_t)node * 3 + 2];
            int c0 = (tid & 3) * 16;
            #pragma unroll
            for (int c = c0; c < c0 + 16; c++) {
                g_P1[(size_t)node * C + c] =
                    px * pos_w1[c * 3 + 0] + py * pos_w1[c * 3 + 1] + pz * pos_w1[c * 3 + 2];
            }
        }
    }
    __syncthreads();

    int r0 = (wid & 3) * 16;
    int nh = wid >> 2;
    int n0 = nh * 32;
    int rA = lane >> 2;
    int cb = 2 * (lane & 3);
    int rowg0 = base + r0 + rA;
    int rowg1 = rowg0 + 8;
    bool ok0 = rowg0 < n, ok1 = rowg1 < n;

    // ---- GEMM1: h = relu(x @ Win^T + b_in) ----
    {
        float acc[4][4];
        #pragma unroll
        for (int nt = 0; nt < 4; nt++) {
            int col = n0 + nt * 8 + cb;
            float b0 = b_in[col], b1 = b_in[col + 1];
            acc[nt][0] = b0; acc[nt][1] = b1; acc[nt][2] = b0; acc[nt][3] = b1;
        }
        #pragma unroll
        for (int kt = 0; kt < 8; kt++) {
            int cA = kt * 8 + (lane & 3);
            unsigned a[4];
            a[0] = __float_as_uint(xs[(r0 + rA) * 68 + cA]);
            a[1] = __float_as_uint(xs[(r0 + 8 + rA) * 68 + cA]);
            a[2] = __float_as_uint(xs[(r0 + rA) * 68 + cA + 4]);
            a[3] = __float_as_uint(xs[(r0 + 8 + rA) * 68 + cA + 4]);
            #pragma unroll
            for (int nt = 0; nt < 4; nt++) {
                float2 b = ((const float2*)g_fWin)[(kt * 8 + nh * 4 + nt) * 32 + lane];
                MMA_TF32(acc[nt], a, __float_as_uint(b.x), __float_as_uint(b.y));
            }
        }
        #pragma unroll
        for (int nt = 0; nt < 4; nt++) {
            int col = n0 + nt * 8 + cb;
            hs[(r0 + rA) * 68 + col]       = __uint_as_float(f2tf32(fmaxf(acc[nt][0], 0.f)));
            hs[(r0 + rA) * 68 + col + 1]   = __uint_as_float(f2tf32(fmaxf(acc[nt][1], 0.f)));
            hs[(r0 + 8 + rA) * 68 + col]     = __uint_as_float(f2tf32(fmaxf(acc[nt][2], 0.f)));
            hs[(r0 + 8 + rA) * 68 + col + 1] = __uint_as_float(f2tf32(fmaxf(acc[nt][3], 0.f)));
        }
    }
    __syncthreads();

    // ---- GEMM2a: v = h @ Wlin^T -> vs (smem) + g_v (global) ----
    {
        float acc[4][4];
        #pragma unroll
        for (int nt = 0; nt < 4; nt++)
            #pragma unroll
            for (int q = 0; q < 4; q++) acc[nt][q] = 0.f;
        #pragma unroll
        for (int kt = 0; kt < 8; kt++) {
            int cA = kt * 8 + (lane & 3);
            unsigned a[4];
            a[0] = __float_as_uint(hs[(r0 + rA) * 68 + cA]);
            a[1] = __float_as_uint(hs[(r0 + 8 + rA) * 68 + cA]);
            a[2] = __float_as_uint(hs[(r0 + rA) * 68 + cA + 4]);
            a[3] = __float_as_uint(hs[(r0 + 8 + rA) * 68 + cA + 4]);
            #pragma unroll
            for (int nt = 0; nt < 4; nt++) {
                float2 b = ((const float2*)g_fWlin)[(kt * 8 + nh * 4 + nt) * 32 + lane];
                MMA_TF32(acc[nt], a, __float_as_uint(b.x), __float_as_uint(b.y));
            }
        }
        #pragma unroll
        for (int nt = 0; nt < 4; nt++) {
            int col = n0 + nt * 8 + cb;
            vs[(r0 + rA) * 68 + col]         = acc[nt][0];
            vs[(r0 + rA) * 68 + col + 1]     = acc[nt][1];
            vs[(r0 + 8 + rA) * 68 + col]     = acc[nt][2];
            vs[(r0 + 8 + rA) * 68 + col + 1] = acc[nt][3];
            if (ok0) *(float2*)(g_v + (size_t)rowg0 * C + col) = make_float2(acc[nt][0], acc[nt][1]);
            if (ok1) *(float2*)(g_v + (size_t)rowg1 * C + col) = make_float2(acc[nt][2], acc[nt][3]);
        }
    }
    // ---- GEMM2b: q = h@Mq^T, k = h@Mk^T; a = relu(q-k+b1) -> xs; q,k -> global --
    {
        float aq[4][4], ak[4][4];
        #pragma unroll
        for (int nt = 0; nt < 4; nt++)
            #pragma unroll
            for (int q = 0; q < 4; q++) { aq[nt][q] = 0.f; ak[nt][q] = 0.f; }
        #pragma unroll
        for (int kt = 0; kt < 8; kt++) {
            int cA = kt * 8 + (lane & 3);
            unsigned a[4];
            a[0] = __float_as_uint(hs[(r0 + rA) * 68 + cA]);
            a[1] = __float_as_uint(hs[(r0 + 8 + rA) * 68 + cA]);
            a[2] = __float_as_uint(hs[(r0 + rA) * 68 + cA + 4]);
            a[3] = __float_as_uint(hs[(r0 + 8 + rA) * 68 + cA + 4]);
            #pragma unroll
            for (int nt = 0; nt < 4; nt++) {
                float2 bq = ((const float2*)g_fMq)[(kt * 8 + nh * 4 + nt) * 32 + lane];
                float2 bk = ((const float2*)g_fMk)[(kt * 8 + nh * 4 + nt) * 32 + lane];
                MMA_TF32(aq[nt], a, __float_as_uint(bq.x), __float_as_uint(bq.y));
                MMA_TF32(ak[nt], a, __float_as_uint(bk.x), __float_as_uint(bk.y));
            }
        }
        #pragma unroll
        for (int nt = 0; nt < 4; nt++) {
            int col = n0 + nt * 8 + cb;
            float ba0 = att_b1[col], ba1 = att_b1[col + 1];
            xs[(r0 + rA) * 68 + col]       = __uint_as_float(f2tf32(fmaxf(aq[nt][0] - ak[nt][0] + ba0, 0.f)));
            xs[(r0 + rA) * 68 + col + 1]   = __uint_as_float(f2tf32(fmaxf(aq[nt][1] - ak[nt][1] + ba1, 0.f)));
            xs[(r0 + 8 + rA) * 68 + col]     = __uint_as_float(f2tf32(fmaxf(aq[nt][2] - ak[nt][2] + ba0, 0.f)));
            xs[(r0 + 8 + rA) * 68 + col + 1] = __uint_as_float(f2tf32(fmaxf(aq[nt][3] - ak[nt][3] + ba1, 0.f)));
            if (ok0) {
                *(float2*)(g_Q1 + (size_t)rowg0 * C + col) = make_float2(aq[nt][0], aq[nt][1]);
                *(float2*)(g_K1 + (size_t)rowg0 * C + col) = make_float2(ak[nt][0], ak[nt][1]);
            }
            if (ok1) {
                *(float2*)(g_Q1 + (size_t)rowg1 * C + col) = make_float2(aq[nt][2], aq[nt][3]);
                *(float2*)(g_K1 + (size_t)rowg1 * C + col) = make_float2(ak[nt][2], ak[nt][3]);
            }
        }
    }
    __syncthreads();

    // ---- GEMM3: s = a @ W2a^T + b2; e = exp(relu(s)); init num/den ----
    {
        float acc[4][4];
        #pragma unroll
        for (int nt = 0; nt < 4; nt++) {
            int col = n0 + nt * 8 + cb;
            float b0 = att_b2[col], b1 = att_b2[col + 1];
            acc[nt][0] = b0; acc[nt][1] = b1; acc[nt][2] = b0; acc[nt][3] = b1;
        }
        #pragma unroll
        for (int kt = 0; kt < 8; kt++) {
            int cA = kt * 8 + (lane & 3);
            unsigned a[4];
            a[0] = __float_as_uint(xs[(r0 + rA) * 68 + cA]);
            a[1] = __float_as_uint(xs[(r0 + 8 + rA) * 68 + cA]);
            a[2] = __float_as_uint(xs[(r0 + rA) * 68 + cA + 4]);
            a[3] = __float_as_uint(xs[(r0 + 8 + rA) * 68 + cA + 4]);
            #pragma unroll
            for (int nt = 0; nt < 4; nt++) {
                float2 b = ((const float2*)g_fW2a)[(kt * 8 + nh * 4 + nt) * 32 + lane];
                MMA_TF32(acc[nt], a, __float_as_uint(b.x), __float_as_uint(b.y));
            }
        }
        #pragma unroll
        for (int nt = 0; nt < 4; nt++) {
            int col = n0 + nt * 8 + cb;
            float d0 = g_delta0[col], d1 = g_delta0[col + 1];
            float e0 = __expf(fmaxf(acc[nt][0], 0.f));
            float e1 = __expf(fmaxf(acc[nt][1], 0.f));
            float e2 = __expf(fmaxf(acc[nt][2], 0.f));
            float e3 = __expf(fmaxf(acc[nt][3], 0.f));
            if (ok0) {
                float v0 = vs[(r0 + rA) * 68 + col];
                float v1 = vs[(r0 + rA) * 68 + col + 1];
                *(float2*)(g_den + (size_t)rowg0 * C + col) = make_float2(e0, e1);
                *(float2*)(g_num + (size_t)rowg0 * C + col) = make_float2(e0 * (v0 + d0), e1 * (v1 + d1));
            }
            if (ok1) {
                float v2 = vs[(r0 + 8 + rA) * 68 + col];
                float v3 = vs[(r0 + 8 + rA) * 68 + col + 1];
                *(float2*)(g_den + (size_t)rowg1 * C + col) = make_float2(e2, e3);
                *(float2*)(g_num + (size_t)rowg1 * C + col) = make_float2(e2 * (v2 + d0), e3 * (v3 + d1));
            }
        }
    }
}

// ---------------- K2: edge kernel — unchanged (tf32 MMA + red.v4) ---------------
__global__ void __launch_bounds__(256, 2)
edge_kernel(const int* __restrict__ src, const int* __restrict__ dst,
            const float* __restrict__ att_b1, const float* __restrict__ pos_b1,
            const float* __restrict__ att_b2, const float* __restrict__ pos_b2,
            int E)
{
    __shared__ float hidA[64 * 68];
    __shared__ float hidP[64 * 68];
    __shared__ int se[64], de[64];

    int tid  = threadIdx.x;
    int lane = tid & 31;
    int wid  = tid >> 5;
    bool isA = (wid < 4);
    int sub  = wid & 3;
    int n0b  = (sub & 1) * 32;
    int mp   = sub >> 1;
    int r0   = mp * 16;
    int r1   = (mp + 2) * 16;

    const float* w2 = isA ? g_w2a_t : g_w2p_t;
    const float* b2 = isA ? att_b2 : pos_b2;
    float* hid = isA ? hidA : hidP;

    unsigned bB[8][4][2];
    #pragma unroll
    for (int kt = 0; kt < 8; kt++) {
        #pragma unroll
        for (int nt = 0; nt < 4; nt++) {
            int k0 = kt * 8, n0 = n0b + nt * 8;
            bB[kt][nt][0] = f2tf32(w2[(k0 + (lane & 3)) * 64 + n0 + (lane >> 2)]);
            bB[kt][nt][1] = f2tf32(w2[(k0 + (lane & 3) + 4) * 64 + n0 + (lane >> 2)]);
        }
    }
    float bias0[4], bias1[4];
    #pragma unroll
    for (int nt = 0; nt < 4; nt++) {
        int col = n0b + nt * 8 + 2 * (lane & 3);
        bias0[nt] = b2[col];
        bias1[nt] = b2[col + 1];
    }

    int ntiles = (E + 63) >> 6;
    for (int tile = blockIdx.x; tile < ntiles; tile += gridDim.x) {
        int base = tile << 6;
        if (tid < 64) {
            int e = base + tid;
            if (e < E) { se[tid] = src[e]; de[tid] = dst[e]; }
            else       { se[tid] = 0;      de[tid] = -1;     }
        }
        __syncthreads();

        {
            int e  = tid >> 2;
            int j0 = (tid & 3) << 4;
            int d  = de[e];
            int dc = d < 0 ? 0 : d;
            int s  = se[e];
            const float* Qr = g_Q1 + (size_t)dc * C;
            const float* Kr = g_K1 + (size_t)s  * C;
            const float* Pd = g_P1 + (size_t)dc * C;
            const float* Ps = g_P1 + (size_t)s  * C;
            #pragma unroll
            for (int gq = 0; gq < 4; gq++) {
                int j = j0 + gq * 4;
                float4 qv = *(const float4*)(Qr + j);
                float4 kv = *(const float4*)(Kr + j);
                float4 ba = *(const float4*)(att_b1 + j);
                float4 r;
                r.x = __uint_as_float(f2tf32(fmaxf(qv.x - kv.x + ba.x, 0.f)));
                r.y = __uint_as_float(f2tf32(fmaxf(qv.y - kv.y + ba.y, 0.f)));
                r.z = __uint_as_float(f2tf32(fmaxf(qv.z - kv.z + ba.z, 0.f)));
                r.w = __uint_as_float(f2tf32(fmaxf(qv.w - kv.w + ba.w, 0.f)));
                *(float4*)(hidA + e * 68 + j) = r;
                float4 pd = *(const float4*)(Pd + j);
                float4 ps = *(const float4*)(Ps + j);
                float4 bp = *(const float4*)(pos_b1 + j);
                r.x = __uint_as_float(f2tf32(fmaxf(pd.x - ps.x + bp.x, 0.f)));
                r.y = __uint_as_float(f2tf32(fmaxf(pd.y - ps.y + bp.y, 0.f)));
                r.z = __uint_as_float(f2tf32(fmaxf(pd.z - ps.z + bp.z, 0.f)));
                r.w = __uint_as_float(f2tf32(fmaxf(pd.w - ps.w + bp.w, 0.f)));
                *(float4*)(hidP + e * 68 + j) = r;
            }
        }
        __syncthreads();

        float acc[2][4][4];
        #pragma unroll
        for (int s2 = 0; s2 < 2; s2++)
            #pragma unroll
            for (int nt = 0; nt < 4; nt++) {
                acc[s2][nt][0] = bias0[nt];
                acc[s2][nt][1] = bias1[nt];
                acc[s2][nt][2] = bias0[nt];
                acc[s2][nt][3] = bias1[nt];
            }
        int rA = lane >> 2;
        #pragma unroll
        for (int kt = 0; kt < 8; kt++) {
            int cA = kt * 8 + (lane & 3);
            unsigned a[2][4];
            a[0][0] = __float_as_uint(hid[(r0 + rA) * 68 + cA]);
            a[0][1] = __float_as_uint(hid[(r0 + 8 + rA) * 68 + cA]);
            a[0][2] = __float_as_uint(hid[(r0 + rA) * 68 + cA + 4]);
            a[0][3] = __float_as_uint(hid[(r0 + 8 + rA) * 68 + cA + 4]);
            a[1][0] = __float_as_uint(hid[(r1 + rA) * 68 + cA]);
            a[1][1] = __float_as_uint(hid[(r1 + 8 + rA) * 68 + cA]);
            a[1][2] = __float_as_uint(hid[(r1 + rA) * 68 + cA + 4]);
            a[1][3] = __float_as_uint(hid[(r1 + 8 + rA) * 68 + cA + 4]);
            #pragma unroll
            for (int s2 = 0; s2 < 2; s2++)
                #pragma unroll
                for (int nt = 0; nt < 4; nt++)
                    MMA_TF32(acc[s2][nt], a[s2], bB[kt][nt][0], bB[kt][nt][1]);
        }
        __syncthreads();

        {
            int cbv = 2 * (lane & 3);
            #pragma unroll
            for (int s2 = 0; s2 < 2; s2++) {
                int rb = (s2 ? r1 : r0) + rA;
                #pragma unroll
                for (int nt = 0; nt < 4; nt++) {
                    int col = n0b + nt * 8 + cbv;
                    float v0, v1, v2, v3;
                    if (isA) {
                        v0 = __expf(fmaxf(acc[s2][nt][0], 0.f));
                        v1 = __expf(fmaxf(acc[s2][nt][1], 0.f));
                        v2 = __expf(fmaxf(acc[s2][nt][2], 0.f));
                        v3 = __expf(fmaxf(acc[s2][nt][3], 0.f));
                    } else {
                        v0 = fmaxf(acc[s2][nt][0], 0.f);
                        v1 = fmaxf(acc[s2][nt][1], 0.f);
                        v2 = fmaxf(acc[s2][nt][2], 0.f);
                        v3 = fmaxf(acc[s2][nt][3], 0.f);
                    }
                    hid[rb * 68 + col]           = v0;
                    hid[rb * 68 + col + 1]       = v1;
                    hid[(rb + 8) * 68 + col]     = v2;
                    hid[(rb + 8) * 68 + col + 1] = v3;
                }
            }
        }
        __syncthreads();

        {
            int e0 = (tid >> 4) << 2;
            int c0 = (tid & 15) << 2;
            #pragma unroll
            for (int k = 0; k < 4; k++) {
                int e = e0 + k;
                int d = de[e];
                if (d >= 0) {
                    int s = se[e];
                    float4 ex = *(const float4*)(hidA + e * 68 + c0);
                    float4 dl = *(const float4*)(hidP + e * 68 + c0);
                    float4 vv = *(const float4*)(g_v + (size_t)s * C + c0);
                    float n0_ = ex.x * (vv.x + dl.x);
                    float n1_ = ex.y * (vv.y + dl.y);
                    float n2_ = ex.z * (vv.z + dl.z);
                    float n3_ = ex.w * (vv.w + dl.w);
                    float* nr = g_num + (size_t)d * C + c0;
                    float* dr = g_den + (size_t)d * C + c0;
                    asm volatile("red.global.add.v4.f32 [%0], {%1,%2,%3,%4};"
                                 :: "l"(nr), "f"(n0_), "f"(n1_), "f"(n2_), "f"(n3_)
                                 : "memory");
                    asm volatile("red.global.add.v4.f32 [%0], {%1,%2,%3,%4};"
                                 :: "l"(dr), "f"(ex.x), "f"(ex.y), "f"(ex.z), "f"(ex.w)
                                 : "memory");
                }
            }
        }
        __syncthreads();
    }
}

// ---------------- K3: out kernel — tf32 MMA over 64-node tiles ------------------
__global__ void __launch_bounds__(256)
out_kernel(const float* __restrict__ b_out, float* __restrict__ out, int n)
{
    __shared__ float rs[64 * 68];
    int tid  = threadIdx.x;
    int lane = tid & 31;
    int wid  = tid >> 5;
    int base = blockIdx.x * 64;

    for (int t = tid; t < 1024; t += 256) {
        int row = t >> 4;
        int col = (t & 15) * 4;
        int node = base + row;
        float4 r = make_float4(0.f, 0.f, 0.f, 0.f);
        if (node < n) {
            float4 nu = *(const float4*)(g_num + (size_t)node * C + col);
            float4 de = *(const float4*)(g_den + (size_t)node * C + col);
            r.x = __uint_as_float(f2tf32(nu.x / (de.x + 1e-16f)));
            r.y = __uint_as_float(f2tf32(nu.y / (de.y + 1e-16f)));
            r.z = __uint_as_float(f2tf32(nu.z / (de.z + 1e-16f)));
            r.w = __uint_as_float(f2tf32(nu.w / (de.w + 1e-16f)));
        }
        *(float4*)(rs + row * 68 + col) = r;
    }
    __syncthreads();

    int r0 = (wid & 3) * 16;
    int nh = wid >> 2;
    int n0 = nh * 32;
    int rA = lane >> 2;
    int cb = 2 * (lane & 3);
    int rowg0 = base + r0 + rA;
    int rowg1 = rowg0 + 8;

    float acc[4][4];
    #pragma unroll
    for (int nt = 0; nt < 4; nt++) {
        int col = n0 + nt * 8 + cb;
        float b0 = b_out[col], b1 = b_out[col + 1];
        acc[nt][0] = b0; acc[nt][1] = b1; acc[nt][2] = b0; acc[nt][3] = b1;
    }
    #pragma unroll
    for (int kt = 0; kt < 8; kt++) {
        int cA = kt * 8 + (lane & 3);
        unsigned a[4];
        a[0] = __float_as_uint(rs[(r0 + rA) * 68 + cA]);
        a[1] = __float_as_uint(rs[(r0 + 8 + rA) * 68 + cA]);
        a[2] = __float_as_uint(rs[(r0 + rA) * 68 + cA + 4]);
        a[3] = __float_as_uint(rs[(r0 + 8 + rA) * 68 + cA + 4]);
        #pragma unroll
        for (int nt = 0; nt < 4; nt++) {
            float2 b = ((const float2*)g_fWout)[(kt * 8 + nh * 4 + nt) * 32 + lane];
            MMA_TF32(acc[nt], a, __float_as_uint(b.x), __float_as_uint(b.y));
        }
    }
    #pragma unroll
    for (int nt = 0; nt < 4; nt++) {
        int col = n0 + nt * 8 + cb;
        if (rowg0 < n)
            *(float2*)(out + (size_t)rowg0 * C + col) =
                make_float2(fmaxf(acc[nt][0], 0.f), fmaxf(acc[nt][1], 0.f));
        if (rowg1 < n)
            *(float2*)(out + (size_t)rowg1 * C + col) =
                make_float2(fmaxf(acc[nt][2], 0.f), fmaxf(acc[nt][3], 0.f));
    }
}

// ---------------- launch --------------------------------------------------------
extern "C" void kernel_launch(void* const* d_in, const int* in_sizes, int n_in,
                              void* d_out, int out_size)
{
    const float* x      = (const float*)d_in[0];
    const float* pos    = (const float*)d_in[1];
    const int*   ei     = (const int*)  d_in[2];
    const float* W_in   = (const float*)d_in[3];
    const float* b_in   = (const float*)d_in[4];
    const float* W_out  = (const float*)d_in[5];
    const float* b_out  = (const float*)d_in[6];
    const float* W_lin  = (const float*)d_in[7];
    const float* W_src  = (const float*)d_in[8];
    const float* W_dst  = (const float*)d_in[9];
    const float* pos_w1 = (const float*)d_in[10];
    const float* pos_b1 = (const float*)d_in[11];
    const float* pos_w2 = (const float*)d_in[12];
    const float* pos_b2 = (const float*)d_in[13];
    const float* att_w1 = (const float*)d_in[14];
    const float* att_b1 = (const float*)d_in[15];
    const float* att_w2 = (const float*)d_in[16];
    const float* att_b2 = (const float*)d_in[17];

    int n = in_sizes[0] / C;
    int E = in_sizes[2] / 2;
    const int* srcArr = ei;
    const int* dstArr = ei + E;

    size_t smemNode = (size_t)(3 * 64 * 68) * sizeof(float);   // 52224
    cudaFuncSetAttribute(node_kernel, cudaFuncAttributeMaxDynamicSharedMemorySize, (int)smemNode);

    int tilesN = (n + 63) / 64;

    prep_kernel<<<1, 256>>>(att_w1, W_dst, W_src, W_in, W_lin, att_w2, pos_w2, W_out,
                            pos_b1, pos_b2);
    node_kernel<<<tilesN, 256, smemNode>>>(x, pos, pos_w1, b_in, att_b1, att_b2, n);
    edge_kernel<<<592, 256>>>(srcArr, dstArr, att_b1, pos_b1, att_b2, pos_b2, E);
    out_kernel<<<tilesN, 256>>>(b_out, (float*)d_out, n);
}

// round 5
// speedup vs baseline: 2.1363x; 1.1691x over previous
#include <cuda_runtime.h>
#include <cstdint>

#define C 64
#define MAXN 50000
#define MAXE 800000

// ---------------- device scratch (static: no allocation allowed) ----------------
__device__ float g_v[MAXN * C];
__device__ float g_Q1[MAXN * C];
__device__ float g_K1[MAXN * C];
__device__ float g_P1[MAXN * C];
__device__ float g_num[MAXN * C];
__device__ float g_den[MAXN * C];
__device__ float g_Mq_t[C * C];
__device__ float g_Mk_t[C * C];
__device__ float g_Win_t[C * C];
__device__ float g_Wlin_t[C * C];
__device__ float g_w2a_t[C * C];
__device__ float g_w2p_t[C * C];
__device__ float g_Wout_t[C * C];
__device__ float g_delta0[C];
// fragment-ordered tf32 weights: [(kt*8+nt)*32+lane] -> float2 (k, k+4)
__device__ float g_fWin[4096];
__device__ float g_fWlin[4096];
__device__ float g_fMq[4096];
__device__ float g_fMk[4096];
__device__ float g_fW2a[4096];
__device__ float g_fWout[4096];

__device__ __forceinline__ unsigned f2tf32(float f) {
    unsigned r;
    asm("cvt.rna.tf32.f32 %0, %1;" : "=r"(r) : "f"(f));
    return r;
}

#define MMA_TF32(d, a, b0, b1)                                               \
    asm volatile("mma.sync.aligned.m16n8k8.row.col.f32.tf32.tf32.f32 "       \
                 "{%0,%1,%2,%3}, {%4,%5,%6,%7}, {%8,%9}, {%0,%1,%2,%3};"     \
                 : "+f"(d[0]), "+f"(d[1]), "+f"(d[2]), "+f"(d[3])            \
                 : "r"(a[0]), "r"(a[1]), "r"(a[2]), "r"(a[3]),               \
                   "r"(b0), "r"(b1))

// ---------------- K0: weight prep ------------------------------------------------
__global__ void prep_kernel(const float* __restrict__ att_w1,
                            const float* __restrict__ W_dst,
                            const float* __restrict__ W_src,
                            const float* __restrict__ W_in,
                            const float* __restrict__ W_lin,
                            const float* __restrict__ att_w2,
                            const float* __restrict__ pos_w2,
                            const float* __restrict__ W_out,
                            const float* __restrict__ pos_b1,
                            const float* __restrict__ pos_b2)
{
    __shared__ float s_a[C * C];
    __shared__ float s_d[C * C];
    __shared__ float s_s[C * C];
    int tid = threadIdx.x;
    for (int t = tid; t < C * C; t += blockDim.x) {
        s_a[t] = att_w1[t];
        s_d[t] = W_dst[t];
        s_s[t] = W_src[t];
    }
    __syncthreads();
    for (int idx = tid; idx < C * C; idx += blockDim.x) {
        int t = idx >> 6, j = idx & 63;
        float aq = 0.f, ak = 0.f;
        #pragma unroll 8
        for (int u = 0; u < C; u++) {
            float a = s_a[t * C + u];
            aq = fmaf(a, s_d[u * C + j], aq);
            ak = fmaf(a, s_s[u * C + j], ak);
        }
        g_Mq_t[j * C + t] = aq;
        g_Mk_t[j * C + t] = ak;
    }
    for (int idx = tid; idx < C * C; idx += blockDim.x) {
        int cc = idx >> 6, j = idx & 63;
        g_Win_t[j * C + cc]  = W_in[idx];
        g_Wlin_t[j * C + cc] = W_lin[idx];
        g_w2a_t[j * C + cc]  = att_w2[idx];
        g_w2p_t[j * C + cc]  = pos_w2[idx];
        g_Wout_t[j * C + cc] = W_out[idx];
    }
    if (tid < C) {
        float acc = pos_b2[tid];
        #pragma unroll 8
        for (int j = 0; j < C; j++)
            acc = fmaf(fmaxf(pos_b1[j], 0.f), pos_w2[tid * C + j], acc);
        g_delta0[tid] = fmaxf(acc, 0.f);
    }
    __syncthreads();
    for (int t = tid; t < 2048; t += blockDim.x) {
        int kt   = t >> 8;
        int nt   = (t >> 5) & 7;
        int lane = t & 31;
        int kr = kt * 8 + (lane & 3);
        int nc = nt * 8 + (lane >> 2);
        int lo = kr * 64 + nc, hi = (kr + 4) * 64 + nc;
        ((float2*)g_fWin)[t]  = make_float2(__uint_as_float(f2tf32(g_Win_t[lo])),
                                            __uint_as_float(f2tf32(g_Win_t[hi])));
        ((float2*)g_fWlin)[t] = make_float2(__uint_as_float(f2tf32(g_Wlin_t[lo])),
                                            __uint_as_float(f2tf32(g_Wlin_t[hi])));
        ((float2*)g_fMq)[t]   = make_float2(__uint_as_float(f2tf32(g_Mq_t[lo])),
                                            __uint_as_float(f2tf32(g_Mq_t[hi])));
        ((float2*)g_fMk)[t]   = make_float2(__uint_as_float(f2tf32(g_Mk_t[lo])),
                                            __uint_as_float(f2tf32(g_Mk_t[hi])));
        ((float2*)g_fW2a)[t]  = make_float2(__uint_as_float(f2tf32(g_w2a_t[lo])),
                                            __uint_as_float(f2tf32(g_w2a_t[hi])));
        ((float2*)g_fWout)[t] = make_float2(__uint_as_float(f2tf32(g_Wout_t[lo])),
                                            __uint_as_float(f2tf32(g_Wout_t[hi])));
    }
}

// ---------------- K1: node kernel — 5 fused tf32 GEMMs over 64-node tiles -------
__global__ void __launch_bounds__(256)
node_kernel(const float* __restrict__ x,
            const float* __restrict__ pos,
            const float* __restrict__ pos_w1,
            const float* __restrict__ b_in,
            const float* __restrict__ att_b1,
            const float* __restrict__ att_b2,
            int n)
{
    extern __shared__ float sm[];
    float* xs = sm;
    float* hs = sm + 4352;
    float* vs = sm + 8704;
    int tid  = threadIdx.x;
    int lane = tid & 31;
    int wid  = tid >> 5;
    int base = blockIdx.x * 64;

    for (int t = tid; t < 1024; t += 256) {
        int row = t >> 4;
        int col = (t & 15) * 4;
        int node = base + row;
        float4 v4 = make_float4(0.f, 0.f, 0.f, 0.f);
        if (node < n) v4 = *(const float4*)(x + (size_t)node * C + col);
        float4 r;
        r.x = __uint_as_float(f2tf32(v4.x));
        r.y = __uint_as_float(f2tf32(v4.y));
        r.z = __uint_as_float(f2tf32(v4.z));
        r.w = __uint_as_float(f2tf32(v4.w));
        *(float4*)(xs + row * 68 + col) = r;
    }
    {
        int row = tid >> 2;
        int node = base + row;
        if (node < n) {
            float px = pos[(size_t)node * 3 + 0];
            float py = pos[(size_t)node * 3 + 1];
            float pz = pos[(size_t)node * 3 + 2];
            int c0 = (tid & 3) * 16;
            #pragma unroll
            for (int c = c0; c < c0 + 16; c++) {
                g_P1[(size_t)node * C + c] =
                    px * pos_w1[c * 3 + 0] + py * pos_w1[c * 3 + 1] + pz * pos_w1[c * 3 + 2];
            }
        }
    }
    __syncthreads();

    int r0 = (wid & 3) * 16;
    int nh = wid >> 2;
    int n0 = nh * 32;
    int rA = lane >> 2;
    int cb = 2 * (lane & 3);
    int rowg0 = base + r0 + rA;
    int rowg1 = rowg0 + 8;
    bool ok0 = rowg0 < n, ok1 = rowg1 < n;

    {
        float acc[4][4];
        #pragma unroll
        for (int nt = 0; nt < 4; nt++) {
            int col = n0 + nt * 8 + cb;
            float b0 = b_in[col], b1 = b_in[col + 1];
            acc[nt][0] = b0; acc[nt][1] = b1; acc[nt][2] = b0; acc[nt][3] = b1;
        }
        #pragma unroll
        for (int kt = 0; kt < 8; kt++) {
            int cA = kt * 8 + (lane & 3);
            unsigned a[4];
            a[0] = __float_as_uint(xs[(r0 + rA) * 68 + cA]);
            a[1] = __float_as_uint(xs[(r0 + 8 + rA) * 68 + cA]);
            a[2] = __float_as_uint(xs[(r0 + rA) * 68 + cA + 4]);
            a[3] = __float_as_uint(xs[(r0 + 8 + rA) * 68 + cA + 4]);
            #pragma unroll
            for (int nt = 0; nt < 4; nt++) {
                float2 b = ((const float2*)g_fWin)[(kt * 8 + nh * 4 + nt) * 32 + lane];
                MMA_TF32(acc[nt], a, __float_as_uint(b.x), __float_as_uint(b.y));
            }
        }
        #pragma unroll
        for (int nt = 0; nt < 4; nt++) {
            int col = n0 + nt * 8 + cb;
            hs[(r0 + rA) * 68 + col]       = __uint_as_float(f2tf32(fmaxf(acc[nt][0], 0.f)));
            hs[(r0 + rA) * 68 + col + 1]   = __uint_as_float(f2tf32(fmaxf(acc[nt][1], 0.f)));
            hs[(r0 + 8 + rA) * 68 + col]     = __uint_as_float(f2tf32(fmaxf(acc[nt][2], 0.f)));
            hs[(r0 + 8 + rA) * 68 + col + 1] = __uint_as_float(f2tf32(fmaxf(acc[nt][3], 0.f)));
        }
    }
    __syncthreads();

    {
        float acc[4][4];
        #pragma unroll
        for (int nt = 0; nt < 4; nt++)
            #pragma unroll
            for (int q = 0; q < 4; q++) acc[nt][q] = 0.f;
        #pragma unroll
        for (int kt = 0; kt < 8; kt++) {
            int cA = kt * 8 + (lane & 3);
            unsigned a[4];
            a[0] = __float_as_uint(hs[(r0 + rA) * 68 + cA]);
            a[1] = __float_as_uint(hs[(r0 + 8 + rA) * 68 + cA]);
            a[2] = __float_as_uint(hs[(r0 + rA) * 68 + cA + 4]);
            a[3] = __float_as_uint(hs[(r0 + 8 + rA) * 68 + cA + 4]);
            #pragma unroll
            for (int nt = 0; nt < 4; nt++) {
                float2 b = ((const float2*)g_fWlin)[(kt * 8 + nh * 4 + nt) * 32 + lane];
                MMA_TF32(acc[nt], a, __float_as_uint(b.x), __float_as_uint(b.y));
            }
        }
        #pragma unroll
        for (int nt = 0; nt < 4; nt++) {
            int col = n0 + nt * 8 + cb;
            vs[(r0 + rA) * 68 + col]         = acc[nt][0];
            vs[(r0 + rA) * 68 + col + 1]     = acc[nt][1];
            vs[(r0 + 8 + rA) * 68 + col]     = acc[nt][2];
            vs[(r0 + 8 + rA) * 68 + col + 1] = acc[nt][3];
            if (ok0) *(float2*)(g_v + (size_t)rowg0 * C + col) = make_float2(acc[nt][0], acc[nt][1]);
            if (ok1) *(float2*)(g_v + (size_t)rowg1 * C + col) = make_float2(acc[nt][2], acc[nt][3]);
        }
    }
    {
        float aq[4][4], ak[4][4];
        #pragma unroll
        for (int nt = 0; nt < 4; nt++)
            #pragma unroll
            for (int q = 0; q < 4; q++) { aq[nt][q] = 0.f; ak[nt][q] = 0.f; }
        #pragma unroll
        for (int kt = 0; kt < 8; kt++) {
            int cA = kt * 8 + (lane & 3);
            unsigned a[4];
            a[0] = __float_as_uint(hs[(r0 + rA) * 68 + cA]);
            a[1] = __float_as_uint(hs[(r0 + 8 + rA) * 68 + cA]);
            a[2] = __float_as_uint(hs[(r0 + rA) * 68 + cA + 4]);
            a[3] = __float_as_uint(hs[(r0 + 8 + rA) * 68 + cA + 4]);
            #pragma unroll
            for (int nt = 0; nt < 4; nt++) {
                float2 bq = ((const float2*)g_fMq)[(kt * 8 + nh * 4 + nt) * 32 + lane];
                float2 bk = ((const float2*)g_fMk)[(kt * 8 + nh * 4 + nt) * 32 + lane];
                MMA_TF32(aq[nt], a, __float_as_uint(bq.x), __float_as_uint(bq.y));
                MMA_TF32(ak[nt], a, __float_as_uint(bk.x), __float_as_uint(bk.y));
            }
        }
        #pragma unroll
        for (int nt = 0; nt < 4; nt++) {
            int col = n0 + nt * 8 + cb;
            float ba0 = att_b1[col], ba1 = att_b1[col + 1];
            xs[(r0 + rA) * 68 + col]       = __uint_as_float(f2tf32(fmaxf(aq[nt][0] - ak[nt][0] + ba0, 0.f)));
            xs[(r0 + rA) * 68 + col + 1]   = __uint_as_float(f2tf32(fmaxf(aq[nt][1] - ak[nt][1] + ba1, 0.f)));
            xs[(r0 + 8 + rA) * 68 + col]     = __uint_as_float(f2tf32(fmaxf(aq[nt][2] - ak[nt][2] + ba0, 0.f)));
            xs[(r0 + 8 + rA) * 68 + col + 1] = __uint_as_float(f2tf32(fmaxf(aq[nt][3] - ak[nt][3] + ba1, 0.f)));
            if (ok0) {
                *(float2*)(g_Q1 + (size_t)rowg0 * C + col) = make_float2(aq[nt][0], aq[nt][1]);
                *(float2*)(g_K1 + (size_t)rowg0 * C + col) = make_float2(ak[nt][0], ak[nt][1]);
            }
            if (ok1) {
                *(float2*)(g_Q1 + (size_t)rowg1 * C + col) = make_float2(aq[nt][2], aq[nt][3]);
                *(float2*)(g_K1 + (size_t)rowg1 * C + col) = make_float2(ak[nt][2], ak[nt][3]);
            }
        }
    }
    __syncthreads();

    {
        float acc[4][4];
        #pragma unroll
        for (int nt = 0; nt < 4; nt++) {
            int col = n0 + nt * 8 + cb;
            float b0 = att_b2[col], b1 = att_b2[col + 1];
            acc[nt][0] = b0; acc[nt][1] = b1; acc[nt][2] = b0; acc[nt][3] = b1;
        }
        #pragma unroll
        for (int kt = 0; kt < 8; kt++) {
            int cA = kt * 8 + (lane & 3);
            unsigned a[4];
            a[0] = __float_as_uint(xs[(r0 + rA) * 68 + cA]);
            a[1] = __float_as_uint(xs[(r0 + 8 + rA) * 68 + cA]);
            a[2] = __float_as_uint(xs[(r0 + rA) * 68 + cA + 4]);
            a[3] = __float_as_uint(xs[(r0 + 8 + rA) * 68 + cA + 4]);
            #pragma unroll
            for (int nt = 0; nt < 4; nt++) {
                float2 b = ((const float2*)g_fW2a)[(kt * 8 + nh * 4 + nt) * 32 + lane];
                MMA_TF32(acc[nt], a, __float_as_uint(b.x), __float_as_uint(b.y));
            }
        }
        #pragma unroll
        for (int nt = 0; nt < 4; nt++) {
            int col = n0 + nt * 8 + cb;
            float d0 = g_delta0[col], d1 = g_delta0[col + 1];
            float e0 = __expf(fmaxf(acc[nt][0], 0.f));
            float e1 = __expf(fmaxf(acc[nt][1], 0.f));
            float e2 = __expf(fmaxf(acc[nt][2], 0.f));
            float e3 = __expf(fmaxf(acc[nt][3], 0.f));
            if (ok0) {
                float v0 = vs[(r0 + rA) * 68 + col];
                float v1 = vs[(r0 + rA) * 68 + col + 1];
                *(float2*)(g_den + (size_t)rowg0 * C + col) = make_float2(e0, e1);
                *(float2*)(g_num + (size_t)rowg0 * C + col) = make_float2(e0 * (v0 + d0), e1 * (v1 + d1));
            }
            if (ok1) {
                float v2 = vs[(r0 + 8 + rA) * 68 + col];
                float v3 = vs[(r0 + 8 + rA) * 68 + col + 1];
                *(float2*)(g_den + (size_t)rowg1 * C + col) = make_float2(e2, e3);
                *(float2*)(g_num + (size_t)rowg1 * C + col) = make_float2(e2 * (v2 + d0), e3 * (v3 + d1));
            }
        }
    }
}

// ---------------- K2: edge kernel — 2-phase pipelined gather/MMA/scatter --------
__global__ void __launch_bounds__(256, 2)
edge_kernel(const int* __restrict__ src, const int* __restrict__ dst,
            const float* __restrict__ att_b1, const float* __restrict__ pos_b1,
            const float* __restrict__ att_b2, const float* __restrict__ pos_b2,
            int E)
{
    extern __shared__ float smE[];
    float* hidA = smE;                 // gather targets (tf32)
    float* hidP = smE + 4352;
    float* exA  = smE + 8704;          // epilogue outputs (exp / delta)
    float* dlP  = smE + 13056;
    int*   seB  = (int*)(smE + 17408); // [2][64] src idx, double-buffered
    int*   deB  = seB + 128;           // [2][64] dst idx

    int tid  = threadIdx.x;
    int lane = tid & 31;
    int wid  = tid >> 5;
    bool isA = (wid < 4);
    int sub  = wid & 3;
    int n0b  = (sub & 1) * 32;
    int mp   = sub >> 1;
    int r0m  = mp * 16;
    int r1m  = (mp + 2) * 16;

    const float* w2 = isA ? g_w2a_t : g_w2p_t;
    const float* b2 = isA ? att_b2 : pos_b2;
    float* hid = isA ? hidA : hidP;
    float* res = isA ? exA  : dlP;

    // --- persistent per-warp B fragments + epilogue biases ---
    unsigned bB[8][4][2];
    #pragma unroll
    for (int kt = 0; kt < 8; kt++) {
        #pragma unroll
        for (int nt = 0; nt < 4; nt++) {
            int k0 = kt * 8, n0 = n0b + nt * 8;
            bB[kt][nt][0] = f2tf32(w2[(k0 + (lane & 3)) * 64 + n0 + (lane >> 2)]);
            bB[kt][nt][1] = f2tf32(w2[(k0 + (lane & 3) + 4) * 64 + n0 + (lane >> 2)]);
        }
    }
    float bias0[4], bias1[4];
    #pragma unroll
    for (int nt = 0; nt < 4; nt++) {
        int col = n0b + nt * 8 + 2 * (lane & 3);
        bias0[nt] = b2[col];
        bias1[nt] = b2[col + 1];
    }

    // --- gather/scatter role: thread owns col slice js for edges {slot+16k} ---
    int slot = tid >> 4;
    int js   = (tid & 15) << 2;
    float4 ba1 = *(const float4*)(att_b1 + js);
    float4 bp1 = *(const float4*)(pos_b1 + js);

    int sPrev[4], dPrev[4];
    #pragma unroll
    for (int k = 0; k < 4; k++) dPrev[k] = -1;

    int ntiles = (E + 63) >> 6;

    // prologue: prefetch first tile's indices into buffer 0
    {
        int base = blockIdx.x << 6;
        if (tid < 64) {
            int e = base + tid;
            seB[tid] = (e < E) ? src[e] : 0;
        } else if (tid < 128) {
            int e = base + tid - 64;
            deB[tid - 64] = (e < E) ? dst[e] : -1;
        }
    }
    __syncthreads();

    int it = 0;
    for (int tile = blockIdx.x; tile < ntiles; tile += gridDim.x, it ^= 1) {
        // ============ PHASE A: scatter(prev) + gather(cur) + prefetch(next) ====
        // scatter of previous tile (fire-and-forget reds)
        #pragma unroll
        for (int k = 0; k < 4; k++) {
            int d = dPrev[k];
            if (d >= 0) {
                int e = slot + 16 * k;
                float4 vv = *(const float4*)(g_v + (size_t)sPrev[k] * C + js);
                float4 ex = *(const float4*)(exA + e * 68 + js);
                float4 dl = *(const float4*)(dlP + e * 68 + js);
                float n0_ = ex.x * (vv.x + dl.x);
                float n1_ = ex.y * (vv.y + dl.y);
                float n2_ = ex.z * (vv.z + dl.z);
                float n3_ = ex.w * (vv.w + dl.w);
                float* nr = g_num + (size_t)d * C + js;
                float* dr = g_den + (size_t)d * C + js;
                asm volatile("red.global.add.v4.f32 [%0], {%1,%2,%3,%4};"
                             :: "l"(nr), "f"(n0_), "f"(n1_), "f"(n2_), "f"(n3_)
                             : "memory");
                asm volatile("red.global.add.v4.f32 [%0], {%1,%2,%3,%4};"
                             :: "l"(dr), "f"(ex.x), "f"(ex.y), "f"(ex.z), "f"(ex.w)
                             : "memory");
            }
        }
        // gather of current tile (16 consecutive lanes read one 256B row)
        #pragma unroll
        for (int k = 0; k < 4; k++) {
            int e = slot + 16 * k;
            int s = seB[it * 64 + e];
            int d = deB[it * 64 + e];
            sPrev[k] = s;
            dPrev[k] = d;
            int dc = d < 0 ? 0 : d;
            float4 qv = *(const float4*)(g_Q1 + (size_t)dc * C + js);
            float4 kv = *(const float4*)(g_K1 + (size_t)s  * C + js);
            float4 ra;
            ra.x = __uint_as_float(f2tf32(fmaxf(qv.x - kv.x + ba1.x, 0.f)));
            ra.y = __uint_as_float(f2tf32(fmaxf(qv.y - kv.y + ba1.y, 0.f)));
            ra.z = __uint_as_float(f2tf32(fmaxf(qv.z - kv.z + ba1.z, 0.f)));
            ra.w = __uint_as_float(f2tf32(fmaxf(qv.w - kv.w + ba1.w, 0.f)));
            float4 pd = *(const float4*)(g_P1 + (size_t)dc * C + js);
            float4 ps = *(const float4*)(g_P1 + (size_t)s  * C + js);
            float4 rp;
            rp.x = __uint_as_float(f2tf32(fmaxf(pd.x - ps.x + bp1.x, 0.f)));
            rp.y = __uint_as_float(f2tf32(fmaxf(pd.y - ps.y + bp1.y, 0.f)));
            rp.z = __uint_as_float(f2tf32(fmaxf(pd.z - ps.z + bp1.z, 0.f)));
            rp.w = __uint_as_float(f2tf32(fmaxf(pd.w - ps.w + bp1.w, 0.f)));
            if (d < 0) {
                ra = make_float4(0.f, 0.f, 0.f, 0.f);
                rp = ra;
            }
            *(float4*)(hidA + e * 68 + js) = ra;
            *(float4*)(hidP + e * 68 + js) = rp;
        }
        // prefetch next tile's indices into the other buffer
        {
            int ntile = tile + gridDim.x;
            if (ntile < ntiles) {
                int base = ntile << 6;
                int ib = (it ^ 1) * 64;
                if (tid < 64) {
                    int e = base + tid;
                    seB[ib + tid] = (e < E) ? src[e] : 0;
                } else if (tid < 128) {
                    int e = base + tid - 64;
                    deB[ib + tid - 64] = (e < E) ? dst[e] : -1;
                }
            }
        }
        __syncthreads();

        // ============ PHASE B: tensor-core MMA + epilogue -> exA/dlP ==========
        float acc[2][4][4];
        #pragma unroll
        for (int s2 = 0; s2 < 2; s2++)
            #pragma unroll
            for (int nt = 0; nt < 4; nt++) {
                acc[s2][nt][0] = bias0[nt];
                acc[s2][nt][1] = bias1[nt];
                acc[s2][nt][2] = bias0[nt];
                acc[s2][nt][3] = bias1[nt];
            }
        int rA = lane >> 2;
        #pragma unroll
        for (int kt = 0; kt < 8; kt++) {
            int cA = kt * 8 + (lane & 3);
            unsigned a[2][4];
            a[0][0] = __float_as_uint(hid[(r0m + rA) * 68 + cA]);
            a[0][1] = __float_as_uint(hid[(r0m + 8 + rA) * 68 + cA]);
            a[0][2] = __float_as_uint(hid[(r0m + rA) * 68 + cA + 4]);
            a[0][3] = __float_as_uint(hid[(r0m + 8 + rA) * 68 + cA + 4]);
            a[1][0] = __float_as_uint(hid[(r1m + rA) * 68 + cA]);
            a[1][1] = __float_as_uint(hid[(r1m + 8 + rA) * 68 + cA]);
            a[1][2] = __float_as_uint(hid[(r1m + rA) * 68 + cA + 4]);
            a[1][3] = __float_as_uint(hid[(r1m + 8 + rA) * 68 + cA + 4]);
            #pragma unroll
            for (int s2 = 0; s2 < 2; s2++)
                #pragma unroll
                for (int nt = 0; nt < 4; nt++)
                    MMA_TF32(acc[s2][nt], a[s2], bB[kt][nt][0], bB[kt][nt][1]);
        }
        {
            int cbv = 2 * (lane & 3);
            #pragma unroll
            for (int s2 = 0; s2 < 2; s2++) {
                int rb = (s2 ? r1m : r0m) + rA;
                #pragma unroll
                for (int nt = 0; nt < 4; nt++) {
                    int col = n0b + nt * 8 + cbv;
                    float v0, v1, v2, v3;
                    if (isA) {
                        v0 = __expf(fmaxf(acc[s2][nt][0], 0.f));
                        v1 = __expf(fmaxf(acc[s2][nt][1], 0.f));
                        v2 = __expf(fmaxf(acc[s2][nt][2], 0.f));
                        v3 = __expf(fmaxf(acc[s2][nt][3], 0.f));
                    } else {
                        v0 = fmaxf(acc[s2][nt][0], 0.f);
                        v1 = fmaxf(acc[s2][nt][1], 0.f);
                        v2 = fmaxf(acc[s2][nt][2], 0.f);
                        v3 = fmaxf(acc[s2][nt][3], 0.f);
                    }
                    res[rb * 68 + col]           = v0;
                    res[rb * 68 + col + 1]       = v1;
                    res[(rb + 8) * 68 + col]     = v2;
                    res[(rb + 8) * 68 + col + 1] = v3;
                }
            }
        }
        __syncthreads();
    }

    // pipeline drain: scatter of the final tile
    #pragma unroll
    for (int k = 0; k < 4; k++) {
        int d = dPrev[k];
        if (d >= 0) {
            int e = slot + 16 * k;
            float4 vv = *(const float4*)(g_v + (size_t)sPrev[k] * C + js);
            float4 ex = *(const float4*)(exA + e * 68 + js);
            float4 dl = *(const float4*)(dlP + e * 68 + js);
            float n0_ = ex.x * (vv.x + dl.x);
            float n1_ = ex.y * (vv.y + dl.y);
            float n2_ = ex.z * (vv.z + dl.z);
            float n3_ = ex.w * (vv.w + dl.w);
            float* nr = g_num + (size_t)d * C + js;
            float* dr = g_den + (size_t)d * C + js;
            asm volatile("red.global.add.v4.f32 [%0], {%1,%2,%3,%4};"
                         :: "l"(nr), "f"(n0_), "f"(n1_), "f"(n2_), "f"(n3_)
                         : "memory");
            asm volatile("red.global.add.v4.f32 [%0], {%1,%2,%3,%4};"
                         :: "l"(dr), "f"(ex.x), "f"(ex.y), "f"(ex.z), "f"(ex.w)
                         : "memory");
        }
    }
}

// ---------------- K3: out kernel — tf32 MMA over 64-node tiles ------------------
__global__ void __launch_bounds__(256)
out_kernel(const float* __restrict__ b_out, float* __restrict__ out, int n)
{
    __shared__ float rs[64 * 68];
    int tid  = threadIdx.x;
    int lane = tid & 31;
    int wid  = tid >> 5;
    int base = blockIdx.x * 64;

    for (int t = tid; t < 1024; t += 256) {
        int row = t >> 4;
        int col = (t & 15) * 4;
        int node = base + row;
        float4 r = make_float4(0.f, 0.f, 0.f, 0.f);
        if (node < n) {
            float4 nu = *(const float4*)(g_num + (size_t)node * C + col);
            float4 de = *(const float4*)(g_den + (size_t)node * C + col);
            r.x = __uint_as_float(f2tf32(nu.x / (de.x + 1e-16f)));
            r.y = __uint_as_float(f2tf32(nu.y / (de.y + 1e-16f)));
            r.z = __uint_as_float(f2tf32(nu.z / (de.z + 1e-16f)));
            r.w = __uint_as_float(f2tf32(nu.w / (de.w + 1e-16f)));
        }
        *(float4*)(rs + row * 68 + col) = r;
    }
    __syncthreads();

    int r0 = (wid & 3) * 16;
    int nh = wid >> 2;
    int n0 = nh * 32;
    int rA = lane >> 2;
    int cb = 2 * (lane & 3);
    int rowg0 = base + r0 + rA;
    int rowg1 = rowg0 + 8;

    float acc[4][4];
    #pragma unroll
    for (int nt = 0; nt < 4; nt++) {
        int col = n0 + nt * 8 + cb;
        float b0 = b_out[col], b1 = b_out[col + 1];
        acc[nt][0] = b0; acc[nt][1] = b1; acc[nt][2] = b0; acc[nt][3] = b1;
    }
    #pragma unroll
    for (int kt = 0; kt < 8; kt++) {
        int cA = kt * 8 + (lane & 3);
        unsigned a[4];
        a[0] = __float_as_uint(rs[(r0 + rA) * 68 + cA]);
        a[1] = __float_as_uint(rs[(r0 + 8 + rA) * 68 + cA]);
        a[2] = __float_as_uint(rs[(r0 + rA) * 68 + cA + 4]);
        a[3] = __float_as_uint(rs[(r0 + 8 + rA) * 68 + cA + 4]);
        #pragma unroll
        for (int nt = 0; nt < 4; nt++) {
            float2 b = ((const float2*)g_fWout)[(kt * 8 + nh * 4 + nt) * 32 + lane];
            MMA_TF32(acc[nt], a, __float_as_uint(b.x), __float_as_uint(b.y));
        }
    }
    #pragma unroll
    for (int nt = 0; nt < 4; nt++) {
        int col = n0 + nt * 8 + cb;
        if (rowg0 < n)
            *(float2*)(out + (size_t)rowg0 * C + col) =
                make_float2(fmaxf(acc[nt][0], 0.f), fmaxf(acc[nt][1], 0.f));
        if (rowg1 < n)
            *(float2*)(out + (size_t)rowg1 * C + col) =
                make_float2(fmaxf(acc[nt][2], 0.f), fmaxf(acc[nt][3], 0.f));
    }
}

// ---------------- launch --------------------------------------------------------
extern "C" void kernel_launch(void* const* d_in, const int* in_sizes, int n_in,
                              void* d_out, int out_size)
{
    const float* x      = (const float*)d_in[0];
    const float* pos    = (const float*)d_in[1];
    const int*   ei     = (const int*)  d_in[2];
    const float* W_in   = (const float*)d_in[3];
    const float* b_in   = (const float*)d_in[4];
    const float* W_out  = (const float*)d_in[5];
    const float* b_out  = (const float*)d_in[6];
    const float* W_lin  = (const float*)d_in[7];
    const float* W_src  = (const float*)d_in[8];
    const float* W_dst  = (const float*)d_in[9];
    const float* pos_w1 = (const float*)d_in[10];
    const float* pos_b1 = (const float*)d_in[11];
    const float* pos_w2 = (const float*)d_in[12];
    const float* pos_b2 = (const float*)d_in[13];
    const float* att_w1 = (const float*)d_in[14];
    const float* att_b1 = (const float*)d_in[15];
    const float* att_w2 = (const float*)d_in[16];
    const float* att_b2 = (const float*)d_in[17];

    int n = in_sizes[0] / C;
    int E = in_sizes[2] / 2;
    const int* srcArr = ei;
    const int* dstArr = ei + E;

    size_t smemNode = (size_t)(3 * 64 * 68) * sizeof(float);          // 52224
    size_t smemEdge = (size_t)(4 * 64 * 68) * sizeof(float) + 1024;   // 70656
    cudaFuncSetAttribute(node_kernel, cudaFuncAttributeMaxDynamicSharedMemorySize, (int)smemNode);
    cudaFuncSetAttribute(edge_kernel, cudaFuncAttributeMaxDynamicSharedMemorySize, (int)smemEdge);

    int tilesN = (n + 63) / 64;

    prep_kernel<<<1, 256>>>(att_w1, W_dst, W_src, W_in, W_lin, att_w2, pos_w2, W_out,
                            pos_b1, pos_b2);
    node_kernel<<<tilesN, 256, smemNode>>>(x, pos, pos_w1, b_in, att_b1, att_b2, n);
    edge_kernel<<<296, 256, smemEdge>>>(srcArr, dstArr, att_b1, pos_b1, att_b2, pos_b2, E);
    out_kernel<<<tilesN, 256>>>(b_out, (float*)d_out, n);
}